// round 1
// baseline (speedup 1.0000x reference)
#include <cuda_runtime.h>
#include <cuda_bf16.h>
#include <cstdint>

// Problem constants
#define BB 2
#define SS 2048
#define DIM 2048
#define NH 16
#define NKV 8
#define HD 128
#define M_ROWS (BB*SS)          // 4096

// ---------------- scratch (device globals: allocation-free) ----------------
__device__ float g_Q[(size_t)M_ROWS * DIM];        // 4096 x 2048
__device__ float g_K[(size_t)M_ROWS * (NKV*HD)];   // 4096 x 1024
__device__ float g_V[(size_t)M_ROWS * (NKV*HD)];   // 4096 x 1024
__device__ float g_ATT[(size_t)M_ROWS * DIM];      // 4096 x 2048

// ---------------- SGEMM: C[M,N] = A[M,K] * B[K,N], row-major, fp32 ----------
// 128x128 block tile, 8 K-slice, 256 threads, 8x8 per thread.
__global__ __launch_bounds__(256) void sgemm128(
    const float* __restrict__ A, const float* __restrict__ B,
    float* __restrict__ C, int M, int N, int K)
{
    __shared__ float As[8][132];
    __shared__ float Bs[8][132];

    const int tid = threadIdx.x;
    const int tx = tid & 15;        // 0..15 -> N
    const int ty = tid >> 4;        // 0..15 -> M
    const int row0 = blockIdx.y * 128;
    const int col0 = blockIdx.x * 128;

    // A tile load mapping: 128 rows x 8 cols -> one float4 per thread
    const int ar = tid >> 1;                // 0..127
    const int ak = (tid & 1) * 4;           // 0 or 4
    // B tile load mapping: 8 rows x 128 cols -> one float4 per thread
    const int bk = tid >> 5;                // 0..7
    const int bc = (tid & 31) * 4;          // 0..124

    float acc[8][8];
    #pragma unroll
    for (int i = 0; i < 8; i++)
        #pragma unroll
        for (int j = 0; j < 8; j++) acc[i][j] = 0.f;

    const float* Ab = A + (size_t)(row0 + ar) * K + ak;
    const float* Bb = B + (size_t)bk * N + col0 + bc;

    for (int k0 = 0; k0 < K; k0 += 8) {
        float4 av = *(const float4*)(Ab + k0);
        As[ak + 0][ar] = av.x;
        As[ak + 1][ar] = av.y;
        As[ak + 2][ar] = av.z;
        As[ak + 3][ar] = av.w;
        float4 bv = *(const float4*)(Bb + (size_t)k0 * N);
        *(float4*)&Bs[bk][bc] = bv;
        __syncthreads();

        #pragma unroll
        for (int kk = 0; kk < 8; kk++) {
            float4 a0 = *(const float4*)&As[kk][ty * 8];
            float4 a1 = *(const float4*)&As[kk][ty * 8 + 4];
            float4 b0 = *(const float4*)&Bs[kk][tx * 8];
            float4 b1 = *(const float4*)&Bs[kk][tx * 8 + 4];
            float ar8[8] = {a0.x,a0.y,a0.z,a0.w,a1.x,a1.y,a1.z,a1.w};
            float br8[8] = {b0.x,b0.y,b0.z,b0.w,b1.x,b1.y,b1.z,b1.w};
            #pragma unroll
            for (int i = 0; i < 8; i++)
                #pragma unroll
                for (int j = 0; j < 8; j++)
                    acc[i][j] += ar8[i] * br8[j];
        }
        __syncthreads();
    }

    #pragma unroll
    for (int i = 0; i < 8; i++) {
        float* Cr = C + (size_t)(row0 + ty * 8 + i) * N + col0 + tx * 8;
        float4 o0 = make_float4(acc[i][0], acc[i][1], acc[i][2], acc[i][3]);
        float4 o1 = make_float4(acc[i][4], acc[i][5], acc[i][6], acc[i][7]);
        *(float4*)(Cr)     = o0;
        *(float4*)(Cr + 4) = o1;
    }
}

// ---------------- RoPE (in-place on g_Q and g_K) ----------------------------
__global__ void rope_kernel(float* __restrict__ Q, float* __restrict__ Kt,
                            const float* __restrict__ cosp,
                            const float* __restrict__ sinp)
{
    const int totalQ = M_ROWS * NH * (HD / 2);
    const int totalK = M_ROWS * NKV * (HD / 2);
    int i = blockIdx.x * blockDim.x + threadIdx.x;
    if (i < totalQ) {
        int j  = i & 63;
        int h  = (i >> 6) & (NH - 1);
        int bs = i >> 10;               // /(64*16)
        int s  = bs & (SS - 1);
        float c  = cosp[s * 64 + j];
        float sn = sinp[s * 64 + j];
        float* p = Q + (size_t)bs * DIM + h * HD + 2 * j;
        float p1 = p[0], p2 = p[1];
        p[0] = p1 * c - p2 * sn;
        p[1] = p1 * sn + p2 * c;
    } else {
        i -= totalQ;
        if (i >= totalK) return;
        int j  = i & 63;
        int h  = (i >> 6) & (NKV - 1);
        int bs = i >> 9;                // /(64*8)
        int s  = bs & (SS - 1);
        float c  = cosp[s * 64 + j];
        float sn = sinp[s * 64 + j];
        float* p = Kt + (size_t)bs * (NKV * HD) + h * HD + 2 * j;
        float p1 = p[0], p2 = p[1];
        p[0] = p1 * c - p2 * sn;
        p[1] = p1 * sn + p2 * c;
    }
}

// ---------------- Flash attention (fp32, BQ=BKV=64, d=128) ------------------
#define QST_LD 68   // transposed Q/K tiles: [128][68]
#define VS_LD 132   // natural V tile: [64][132]
#define SS_LD 65    // score tile: [64][65]
#define KVU_FLOATS 8704   // max(128*68, 64*132)

__global__ __launch_bounds__(256) void attn_kernel(
    const float* __restrict__ Q, const float* __restrict__ K,
    const float* __restrict__ V, float* __restrict__ O)
{
    extern __shared__ float sm[];
    float* Qst = sm;                       // 128*68
    float* KVu = Qst + 128 * QST_LD;       // union: Kst[128][68] / Vs[64][132]
    float* Ssc = KVu + KVU_FLOATS;         // 64*65
    float* m_s = Ssc + 64 * SS_LD;         // 64
    float* l_s = m_s + 64;                 // 64
    float* e_s = l_s + 64;                 // 64

    const int tid = threadIdx.x;
    const int qt  = blockIdx.x;            // 0..31 query tile
    const int bh  = blockIdx.y;            // 0..31
    const int b   = bh >> 4;
    const int h   = bh & 15;
    const int hk  = h >> 1;                // GQA: kv head = h / 2
    const int q0  = qt * 64;
    const float scale = 0.08838834764831845f;  // 1/sqrt(128)

    const float* Qg = Q + ((size_t)b * SS + q0) * DIM + h * HD;      // stride 2048
    const float* Kg = K + (size_t)b * SS * (NKV*HD) + hk * HD;       // stride 1024
    const float* Vg = V + (size_t)b * SS * (NKV*HD) + hk * HD;

    // load Q tile transposed: Qst[d][q]
    {
        const int l = tid & 31, w = tid >> 5;
        const int q  = l + 32 * (w & 1);
        const int db = w >> 1;             // 0..3
        #pragma unroll
        for (int it = 0; it < 8; it++) {
            int d4 = db + 4 * it;
            float4 v = *(const float4*)(Qg + (size_t)q * DIM + d4 * 4);
            Qst[(d4 * 4 + 0) * QST_LD + q] = v.x;
            Qst[(d4 * 4 + 1) * QST_LD + q] = v.y;
            Qst[(d4 * 4 + 2) * QST_LD + q] = v.z;
            Qst[(d4 * 4 + 3) * QST_LD + q] = v.w;
        }
    }
    if (tid < 64) { m_s[tid] = -1e30f; l_s[tid] = 0.f; }

    float acc[32];
    #pragma unroll
    for (int r = 0; r < 32; r++) acc[r] = 0.f;

    const int niter = qt + 1;
    for (int kb = 0; kb < niter; kb++) {
        const int k0 = kb * 64;
        __syncthreads();   // PV of prev iter done; safe to overwrite KVu / Ssc

        // load K tile transposed: Kst[d][kj]
        {
            const int l = tid & 31, w = tid >> 5;
            const int q  = l + 32 * (w & 1);
            const int db = w >> 1;
            #pragma unroll
            for (int it = 0; it < 8; it++) {
                int d4 = db + 4 * it;
                float4 v = *(const float4*)(Kg + (size_t)(k0 + q) * (NKV*HD) + d4 * 4);
                KVu[(d4 * 4 + 0) * QST_LD + q] = v.x;
                KVu[(d4 * 4 + 1) * QST_LD + q] = v.y;
                KVu[(d4 * 4 + 2) * QST_LD + q] = v.z;
                KVu[(d4 * 4 + 3) * QST_LD + q] = v.w;
            }
        }
        __syncthreads();

        // scores: S[64][64] = Q * K^T (16x16 thread grid, 4x4 micro-tile)
        {
            const int txx = tid & 15, tyy = tid >> 4;
            float s[16];
            #pragma unroll
            for (int i = 0; i < 16; i++) s[i] = 0.f;
            #pragma unroll 8
            for (int d = 0; d < 128; d++) {
                float4 aq = *(const float4*)&Qst[d * QST_LD + tyy * 4];
                float4 bk = *(const float4*)&KVu[d * QST_LD + txx * 4];
                s[0]  += aq.x * bk.x; s[1]  += aq.x * bk.y; s[2]  += aq.x * bk.z; s[3]  += aq.x * bk.w;
                s[4]  += aq.y * bk.x; s[5]  += aq.y * bk.y; s[6]  += aq.y * bk.z; s[7]  += aq.y * bk.w;
                s[8]  += aq.z * bk.x; s[9]  += aq.z * bk.y; s[10] += aq.z * bk.z; s[11] += aq.z * bk.w;
                s[12] += aq.w * bk.x; s[13] += aq.w * bk.y; s[14] += aq.w * bk.z; s[15] += aq.w * bk.w;
            }
            const bool diag = (kb == qt);
            #pragma unroll
            for (int i = 0; i < 4; i++) {
                #pragma unroll
                for (int j = 0; j < 4; j++) {
                    int qi = tyy * 4 + i, kj = txx * 4 + j;
                    float v = s[i * 4 + j] * scale;
                    if (diag && kj > qi) v = -1e30f;
                    Ssc[qi * SS_LD + kj] = v;
                }
            }
        }
        __syncthreads();

        // load V tile (natural layout), coalesced — K reads are done
        {
            #pragma unroll
            for (int l2 = 0; l2 < 8; l2++) {
                int idx = tid + 256 * l2;
                int r = idx >> 5, c4 = idx & 31;
                float4 v = *(const float4*)(Vg + (size_t)(k0 + r) * (NKV*HD) + c4 * 4);
                *(float4*)&KVu[r * VS_LD + c4 * 4] = v;
            }
        }
        // online softmax: q = tid/4, 4 lanes per row
        {
            const int q = tid >> 2, p = tid & 3;
            float sv[16];
            float mx = -1e30f;
            #pragma unroll
            for (int kk = 0; kk < 16; kk++) {
                sv[kk] = Ssc[q * SS_LD + p * 16 + kk];
                mx = fmaxf(mx, sv[kk]);
            }
            mx = fmaxf(mx, __shfl_xor_sync(0xffffffffu, mx, 1));
            mx = fmaxf(mx, __shfl_xor_sync(0xffffffffu, mx, 2));
            float mo = m_s[q];
            float mn = fmaxf(mo, mx);
            float sum = 0.f;
            #pragma unroll
            for (int kk = 0; kk < 16; kk++) {
                float pk = __expf(sv[kk] - mn);
                sum += pk;
                Ssc[q * SS_LD + p * 16 + kk] = pk;
            }
            sum += __shfl_xor_sync(0xffffffffu, sum, 1);
            sum += __shfl_xor_sync(0xffffffffu, sum, 2);
            if (p == 0) {
                float es = __expf(mo - mn);
                m_s[q] = mn;
                e_s[q] = es;
                l_s[q] = l_s[q] * es + sum;
            }
        }
        __syncthreads();

        // PV: O[64][128] += P[64][64] * V[64][128]
        {
            const int q = tid & 63, cg = tid >> 6;   // cg: 0..3 (32 cols each)
            float f = e_s[q];
            #pragma unroll
            for (int r = 0; r < 32; r++) acc[r] *= f;
            #pragma unroll 4
            for (int kj = 0; kj < 64; kj++) {
                float p = Ssc[q * SS_LD + kj];
                const float4* vr = (const float4*)&KVu[kj * VS_LD + cg * 32];
                #pragma unroll
                for (int c = 0; c < 8; c++) {
                    float4 v = vr[c];
                    acc[c * 4 + 0] += p * v.x;
                    acc[c * 4 + 1] += p * v.y;
                    acc[c * 4 + 2] += p * v.z;
                    acc[c * 4 + 3] += p * v.w;
                }
            }
        }
    }

    // epilogue: normalize and write O[b][s][h*128 + c]
    {
        const int q = tid & 63, cg = tid >> 6;
        float inv = 1.0f / l_s[q];
        float* Og = O + ((size_t)b * SS + q0 + q) * DIM + h * HD + cg * 32;
        #pragma unroll
        for (int c = 0; c < 8; c++) {
            float4 o = make_float4(acc[c*4+0]*inv, acc[c*4+1]*inv,
                                   acc[c*4+2]*inv, acc[c*4+3]*inv);
            ((float4*)Og)[c] = o;
        }
    }
}

// ---------------- launcher ---------------------------------------------------
extern "C" void kernel_launch(void* const* d_in, const int* in_sizes, int n_in,
                              void* d_out, int out_size)
{
    const float* x    = (const float*)d_in[0];
    const float* fcos = (const float*)d_in[1];
    const float* fsin = (const float*)d_in[2];
    const float* wq   = (const float*)d_in[3];
    const float* wk   = (const float*)d_in[4];
    const float* wv   = (const float*)d_in[5];
    const float* wo   = (const float*)d_in[6];
    float* out = (float*)d_out;

    float *pQ, *pK, *pV, *pA;
    cudaGetSymbolAddress((void**)&pQ, g_Q);
    cudaGetSymbolAddress((void**)&pK, g_K);
    cudaGetSymbolAddress((void**)&pV, g_V);
    cudaGetSymbolAddress((void**)&pA, g_ATT);

    // QKV projections
    sgemm128<<<dim3(DIM/128,      M_ROWS/128), 256>>>(x, wq, pQ, M_ROWS, DIM,    DIM);
    sgemm128<<<dim3((NKV*HD)/128, M_ROWS/128), 256>>>(x, wk, pK, M_ROWS, NKV*HD, DIM);
    sgemm128<<<dim3((NKV*HD)/128, M_ROWS/128), 256>>>(x, wv, pV, M_ROWS, NKV*HD, DIM);

    // RoPE on Q and K
    {
        int total = M_ROWS * (NH + NKV) * (HD / 2);
        rope_kernel<<<(total + 255) / 256, 256>>>(pQ, pK, fcos, fsin);
    }

    // attention
    {
        size_t smem = (size_t)(128 * QST_LD + KVU_FLOATS + 64 * SS_LD + 192) * sizeof(float);
        cudaFuncSetAttribute(attn_kernel, cudaFuncAttributeMaxDynamicSharedMemorySize, (int)smem);
        attn_kernel<<<dim3(SS/64, BB * NH), 256, smem>>>(pQ, pK, pV, pA);
    }

    // output projection
    sgemm128<<<dim3(DIM/128, M_ROWS/128), 256>>>(pA, wo, out, M_ROWS, DIM, DIM);
}

// round 3
// speedup vs baseline: 2.0723x; 2.0723x over previous
#include <cuda_runtime.h>
#include <cuda_bf16.h>
#include <cstdint>

// Problem constants
#define BB 2
#define SS 2048
#define DIM 2048
#define NH 16
#define NKV 8
#define HD 128
#define M_ROWS (BB*SS)          // 4096
#define KTILES 64               // K=2048 / 32

// ---------------- scratch (device globals: allocation-free) ----------------
__device__ float g_Q[(size_t)M_ROWS * DIM];
__device__ float g_K[(size_t)M_ROWS * (NKV*HD)];
__device__ float g_V[(size_t)M_ROWS * (NKV*HD)];
__device__ float g_ATT[(size_t)M_ROWS * DIM];
// packed tf32 fragment-major buffers
__device__ float g_xp  [(size_t)M_ROWS * DIM];
__device__ float g_attp[(size_t)M_ROWS * DIM];
__device__ float g_wqp [(size_t)DIM * DIM];
__device__ float g_wkp [(size_t)DIM * (NKV*HD)];
__device__ float g_wvp [(size_t)DIM * (NKV*HD)];
__device__ float g_wop [(size_t)DIM * DIM];

// ---------------- PTX helpers (base sm_90 / sm_80 features only!) -----------
__device__ __forceinline__ uint32_t smem_u32(const void* p) {
    uint32_t a;
    asm("{ .reg .u64 t; cvta.to.shared.u64 t, %1; cvt.u32.u64 %0, t; }" : "=r"(a) : "l"(p));
    return a;
}
__device__ __forceinline__ float tf32r(float x) {
    uint32_t u;
    asm("cvt.rna.tf32.f32 %0, %1;" : "=r"(u) : "f"(x));
    return __uint_as_float(u);
}

#define MBAR_INIT(a, cnt) \
    asm volatile("mbarrier.init.shared.b64 [%0], %1;" :: "r"(a), "r"(cnt) : "memory")
#define MBAR_EXPECT_TX(a, b) \
    asm volatile("mbarrier.arrive.expect_tx.shared.b64 _, [%0], %1;" :: "r"(a), "r"(b) : "memory")

__device__ __forceinline__ void mbar_wait(uint32_t addr, uint32_t phase) {
    uint32_t done;
    asm volatile(
        "{\n\t.reg .pred p;\n\t"
        "mbarrier.try_wait.parity.acquire.cta.shared::cta.b64 p, [%1], %2;\n\t"
        "selp.b32 %0, 1, 0, p;\n\t}"
        : "=r"(done) : "r"(addr), "r"(phase) : "memory");
    if (!done) {
        asm volatile(
            "{\n\t.reg .pred P1;\n\t"
            "W_%=:\n\t"
            "mbarrier.try_wait.parity.acquire.cta.shared::cta.b64 P1, [%0], %1, 0x989680;\n\t"
            "@P1 bra.uni D_%=;\n\t"
            "bra.uni W_%=;\n\t"
            "D_%=:\n\t}"
            :: "r"(addr), "r"(phase) : "memory");
    }
}
__device__ __forceinline__ void bulk_g2s(uint32_t dst, const void* src, uint32_t bytes, uint32_t mbar) {
    asm volatile(
        "cp.async.bulk.shared::cluster.global.mbarrier::complete_tx::bytes [%0], [%1], %2, [%3];"
        :: "r"(dst), "l"(src), "r"(bytes), "r"(mbar) : "memory");
}
__device__ __forceinline__ void fence_async() {
    asm volatile("fence.proxy.async;" ::: "memory");
}

// m16n8k8 tf32 mma: D = A*B + D (fp32 accum)
__device__ __forceinline__ void mma_tf32(float* c, const uint32_t* a, const uint32_t* b) {
    asm volatile(
        "mma.sync.aligned.m16n8k8.row.col.f32.tf32.tf32.f32 "
        "{%0,%1,%2,%3}, {%4,%5,%6,%7}, {%8,%9}, {%0,%1,%2,%3};"
        : "+f"(c[0]), "+f"(c[1]), "+f"(c[2]), "+f"(c[3])
        : "r"(a[0]), "r"(a[1]), "r"(a[2]), "r"(a[3]), "r"(b[0]), "r"(b[1]));
}
#define LDS128(r, addr) \
    asm volatile("ld.shared.v4.b32 {%0,%1,%2,%3}, [%4];" \
        : "=r"((r)[0]), "=r"((r)[1]), "=r"((r)[2]), "=r"((r)[3]) : "r"(addr))
#define LDS64(r, addr) \
    asm volatile("ld.shared.v2.b32 {%0,%1}, [%2];" \
        : "=r"((r)[0]), "=r"((r)[1]) : "r"(addr))

// ---------------- pack A: [M,K] fp32 -> fragment-major tiles -----------------
// Tile (mt128, kc32): 1024 float4. f = ((ks*8 + mtg)*32 + lane), regs =
// {A[m,k], A[m+8,k], A[m,k+4], A[m+8,k+4]}, m = mt*128+mtg*16+(lane>>2),
// k = kc*32+ks*8+(lane&3).
__global__ __launch_bounds__(256) void pack_A(const float* __restrict__ src,
                                              float* __restrict__ dst, int K)
{
    const int kc = blockIdx.x, mt = blockIdx.y;
    const int tid = threadIdx.x;
    float4* tb = (float4*)(dst + (size_t)(mt * (K / 32) + kc) * 4096);
    #pragma unroll
    for (int t = 0; t < 4; t++) {
        int f = tid + 256 * t;
        int ks = f >> 8, rem = f & 255;
        int mtg = rem >> 5, lane = rem & 31;
        int r = lane >> 2, c = lane & 3;
        int m = mt * 128 + mtg * 16 + r;
        int k = kc * 32 + ks * 8 + c;
        const float* s0 = src + (size_t)m * K + k;
        const float* s1 = s0 + 8 * (size_t)K;
        tb[f] = make_float4(tf32r(s0[0]), tf32r(s1[0]), tf32r(s0[4]), tf32r(s1[4]));
    }
}

// ---------------- pack B: w [K,N] -> fragment-major tiles --------------------
// Tile (nt128, kc32): 2048 float2. f = ((ks*16 + ntg)*32 + lane), regs =
// {w[k,n], w[k+4,n]}, k = kc*32+ks*8+(lane&3), n = nt*128+ntg*8+(lane>>2).
__global__ __launch_bounds__(256) void pack_B(const float* __restrict__ w,
                                              float* __restrict__ dst, int N)
{
    const int kc = blockIdx.x, nt = blockIdx.y;
    const int tid = threadIdx.x;
    float2* tb = (float2*)(dst + (size_t)(nt * KTILES + kc) * 4096);
    #pragma unroll
    for (int t = 0; t < 8; t++) {
        int f = tid + 256 * t;
        int ks = f >> 9, rem = f & 511;
        int ntg = rem >> 5, lane = rem & 31;
        int c = lane & 3, nn = lane >> 2;
        int k = kc * 32 + ks * 8 + c;
        int n = nt * 128 + ntg * 8 + nn;
        tb[f] = make_float2(tf32r(w[(size_t)k * N + n]), tf32r(w[(size_t)(k + 4) * N + n]));
    }
}

// ---------------- mma.sync tf32 GEMM: C[M,N] = Ap * Bp^T ---------------------
// CTA 128x128x32, 3-stage cp.async.bulk ring, 8 warps (2x4), warp tile 64x32.
#define GSTAGES 3
#define STAGE_BYTES 32768   // A 16KB + B 16KB

__global__ __launch_bounds__(256) void gemm_mma(
    const float* __restrict__ Ap, const float* __restrict__ Bp,
    float* __restrict__ C, int Ndim, int kTiles)
{
    extern __shared__ float dyn[];
    __shared__ __align__(8) uint64_t mbar[GSTAGES];

    const int tid  = threadIdx.x;
    const int lane = tid & 31;
    const int warp = tid >> 5;
    const int wm = warp >> 2;       // 0..1
    const int wn = warp & 3;        // 0..3
    const int nt = blockIdx.x, mt = blockIdx.y;

    uint32_t sbase = (smem_u32(dyn) + 1023) & ~1023u;
    uint32_t mb = smem_u32(mbar);
    #define FULLB(s) (mb + (s) * 8)

    if (tid == 0) {
        #pragma unroll
        for (int s = 0; s < GSTAGES; s++) MBAR_INIT(FULLB(s), 1);
    }
    __syncthreads();

    const char* At = (const char*)(Ap + (size_t)mt * kTiles * 4096);
    const char* Bt = (const char*)(Bp + (size_t)nt * kTiles * 4096);

    if (tid == 0) {
        fence_async();
        #pragma unroll
        for (int j = 0; j < GSTAGES; j++) {
            MBAR_EXPECT_TX(FULLB(j), STAGE_BYTES);
            bulk_g2s(sbase + j * STAGE_BYTES,         At + (size_t)j * 16384, 16384, FULLB(j));
            bulk_g2s(sbase + j * STAGE_BYTES + 16384, Bt + (size_t)j * 16384, 16384, FULLB(j));
        }
    }

    float acc[4][4][4];
    #pragma unroll
    for (int i = 0; i < 4; i++)
        #pragma unroll
        for (int j = 0; j < 4; j++)
            #pragma unroll
            for (int q = 0; q < 4; q++) acc[i][j][q] = 0.f;

    for (int i = 0; i < kTiles; i++) {
        const int s = i % GSTAGES;
        const uint32_t ph = (i / GSTAGES) & 1;
        mbar_wait(FULLB(s), ph);
        const uint32_t a_base = sbase + s * STAGE_BYTES;
        const uint32_t b_base = a_base + 16384;

        #pragma unroll
        for (int ks = 0; ks < 4; ks++) {
            uint32_t ar[4][4], br[4][2];
            #pragma unroll
            for (int ii = 0; ii < 4; ii++)
                LDS128(ar[ii], a_base + (uint32_t)(((ks * 8 + wm * 4 + ii) * 32 + lane) * 16));
            #pragma unroll
            for (int jj = 0; jj < 4; jj++)
                LDS64(br[jj], b_base + (uint32_t)(((ks * 16 + wn * 4 + jj) * 32 + lane) * 8));
            #pragma unroll
            for (int ii = 0; ii < 4; ii++)
                #pragma unroll
                for (int jj = 0; jj < 4; jj++)
                    mma_tf32(acc[ii][jj], ar[ii], br[jj]);
        }
        __syncthreads();
        if (tid == 0) {
            int jn = i + GSTAGES;
            if (jn < kTiles) {
                fence_async();
                MBAR_EXPECT_TX(FULLB(s), STAGE_BYTES);
                bulk_g2s(a_base, At + (size_t)jn * 16384, 16384, FULLB(s));
                bulk_g2s(b_base, Bt + (size_t)jn * 16384, 16384, FULLB(s));
            }
        }
    }

    // epilogue
    const int r = lane >> 2, cc = lane & 3;
    #pragma unroll
    for (int ii = 0; ii < 4; ii++) {
        int m0 = mt * 128 + wm * 64 + ii * 16 + r;
        float* row0 = C + (size_t)m0 * Ndim + nt * 128 + wn * 32 + 2 * cc;
        float* row1 = row0 + 8 * (size_t)Ndim;
        #pragma unroll
        for (int jj = 0; jj < 4; jj++) {
            *(float2*)(row0 + jj * 8) = make_float2(acc[ii][jj][0], acc[ii][jj][1]);
            *(float2*)(row1 + jj * 8) = make_float2(acc[ii][jj][2], acc[ii][jj][3]);
        }
    }
}

// ---------------- RoPE (in-place on g_Q and g_K) ----------------------------
__global__ void rope_kernel(float* __restrict__ Q, float* __restrict__ Kt,
                            const float* __restrict__ cosp,
                            const float* __restrict__ sinp)
{
    const int totalQ = M_ROWS * NH * (HD / 2);
    const int totalK = M_ROWS * NKV * (HD / 2);
    int i = blockIdx.x * blockDim.x + threadIdx.x;
    if (i < totalQ) {
        int j  = i & 63;
        int h  = (i >> 6) & (NH - 1);
        int bs = i >> 10;
        int s  = bs & (SS - 1);
        float c  = cosp[s * 64 + j];
        float sn = sinp[s * 64 + j];
        float* p = Q + (size_t)bs * DIM + h * HD + 2 * j;
        float p1 = p[0], p2 = p[1];
        p[0] = p1 * c - p2 * sn;
        p[1] = p1 * sn + p2 * c;
    } else {
        i -= totalQ;
        if (i >= totalK) return;
        int j  = i & 63;
        int h  = (i >> 6) & (NKV - 1);
        int bs = i >> 9;
        int s  = bs & (SS - 1);
        float c  = cosp[s * 64 + j];
        float sn = sinp[s * 64 + j];
        float* p = Kt + (size_t)bs * (NKV * HD) + h * HD + 2 * j;
        float p1 = p[0], p2 = p[1];
        p[0] = p1 * c - p2 * sn;
        p[1] = p1 * sn + p2 * c;
    }
}

// ---------------- Flash attention (fp32, BQ=BKV=64, d=128) ------------------
#define QST_LD 68
#define VS_LD 132
#define SS_LD 65
#define KVU_FLOATS 8704

__global__ __launch_bounds__(256) void attn_kernel(
    const float* __restrict__ Q, const float* __restrict__ K,
    const float* __restrict__ V, float* __restrict__ O)
{
    extern __shared__ float sm[];
    float* Qst = sm;
    float* KVu = Qst + 128 * QST_LD;
    float* Ssc = KVu + KVU_FLOATS;
    float* m_s = Ssc + 64 * SS_LD;
    float* l_s = m_s + 64;
    float* e_s = l_s + 64;

    const int tid = threadIdx.x;
    const int qt  = blockIdx.x;
    const int bh  = blockIdx.y;
    const int b   = bh >> 4;
    const int h   = bh & 15;
    const int hk  = h >> 1;
    const int q0  = qt * 64;
    const float scale = 0.08838834764831845f;

    const float* Qg = Q + ((size_t)b * SS + q0) * DIM + h * HD;
    const float* Kg = K + (size_t)b * SS * (NKV*HD) + hk * HD;
    const float* Vg = V + (size_t)b * SS * (NKV*HD) + hk * HD;

    {
        const int l = tid & 31, w = tid >> 5;
        const int q  = l + 32 * (w & 1);
        const int db = w >> 1;
        #pragma unroll
        for (int it = 0; it < 8; it++) {
            int d4 = db + 4 * it;
            float4 v = *(const float4*)(Qg + (size_t)q * DIM + d4 * 4);
            Qst[(d4 * 4 + 0) * QST_LD + q] = v.x;
            Qst[(d4 * 4 + 1) * QST_LD + q] = v.y;
            Qst[(d4 * 4 + 2) * QST_LD + q] = v.z;
            Qst[(d4 * 4 + 3) * QST_LD + q] = v.w;
        }
    }
    if (tid < 64) { m_s[tid] = -1e30f; l_s[tid] = 0.f; }

    float acc[32];
    #pragma unroll
    for (int r = 0; r < 32; r++) acc[r] = 0.f;

    const int niter = qt + 1;
    for (int kb = 0; kb < niter; kb++) {
        const int k0 = kb * 64;
        __syncthreads();

        {
            const int l = tid & 31, w = tid >> 5;
            const int q  = l + 32 * (w & 1);
            const int db = w >> 1;
            #pragma unroll
            for (int it = 0; it < 8; it++) {
                int d4 = db + 4 * it;
                float4 v = *(const float4*)(Kg + (size_t)(k0 + q) * (NKV*HD) + d4 * 4);
                KVu[(d4 * 4 + 0) * QST_LD + q] = v.x;
                KVu[(d4 * 4 + 1) * QST_LD + q] = v.y;
                KVu[(d4 * 4 + 2) * QST_LD + q] = v.z;
                KVu[(d4 * 4 + 3) * QST_LD + q] = v.w;
            }
        }
        __syncthreads();

        {
            const int txx = tid & 15, tyy = tid >> 4;
            float s[16];
            #pragma unroll
            for (int i = 0; i < 16; i++) s[i] = 0.f;
            #pragma unroll 8
            for (int d = 0; d < 128; d++) {
                float4 aq = *(const float4*)&Qst[d * QST_LD + tyy * 4];
                float4 bk = *(const float4*)&KVu[d * QST_LD + txx * 4];
                s[0]  += aq.x * bk.x; s[1]  += aq.x * bk.y; s[2]  += aq.x * bk.z; s[3]  += aq.x * bk.w;
                s[4]  += aq.y * bk.x; s[5]  += aq.y * bk.y; s[6]  += aq.y * bk.z; s[7]  += aq.y * bk.w;
                s[8]  += aq.z * bk.x; s[9]  += aq.z * bk.y; s[10] += aq.z * bk.z; s[11] += aq.z * bk.w;
                s[12] += aq.w * bk.x; s[13] += aq.w * bk.y; s[14] += aq.w * bk.z; s[15] += aq.w * bk.w;
            }
            const bool diag = (kb == qt);
            #pragma unroll
            for (int i = 0; i < 4; i++) {
                #pragma unroll
                for (int j = 0; j < 4; j++) {
                    int qi = tyy * 4 + i, kj = txx * 4 + j;
                    float v = s[i * 4 + j] * scale;
                    if (diag && kj > qi) v = -1e30f;
                    Ssc[qi * SS_LD + kj] = v;
                }
            }
        }
        __syncthreads();

        {
            #pragma unroll
            for (int l2 = 0; l2 < 8; l2++) {
                int idx = tid + 256 * l2;
                int r = idx >> 5, c4 = idx & 31;
                float4 v = *(const float4*)(Vg + (size_t)(k0 + r) * (NKV*HD) + c4 * 4);
                *(float4*)&KVu[r * VS_LD + c4 * 4] = v;
            }
        }
        {
            const int q = tid >> 2, p = tid & 3;
            float sv[16];
            float mx = -1e30f;
            #pragma unroll
            for (int kk = 0; kk < 16; kk++) {
                sv[kk] = Ssc[q * SS_LD + p * 16 + kk];
                mx = fmaxf(mx, sv[kk]);
            }
            mx = fmaxf(mx, __shfl_xor_sync(0xffffffffu, mx, 1));
            mx = fmaxf(mx, __shfl_xor_sync(0xffffffffu, mx, 2));
            float mo = m_s[q];
            float mn = fmaxf(mo, mx);
            float sum = 0.f;
            #pragma unroll
            for (int kk = 0; kk < 16; kk++) {
                float pk = __expf(sv[kk] - mn);
                sum += pk;
                Ssc[q * SS_LD + p * 16 + kk] = pk;
            }
            sum += __shfl_xor_sync(0xffffffffu, sum, 1);
            sum += __shfl_xor_sync(0xffffffffu, sum, 2);
            if (p == 0) {
                float es = __expf(mo - mn);
                m_s[q] = mn;
                e_s[q] = es;
                l_s[q] = l_s[q] * es + sum;
            }
        }
        __syncthreads();

        {
            const int q = tid & 63, cg = tid >> 6;
            float f = e_s[q];
            #pragma unroll
            for (int r = 0; r < 32; r++) acc[r] *= f;
            #pragma unroll 4
            for (int kj = 0; kj < 64; kj++) {
                float p = Ssc[q * SS_LD + kj];
                const float4* vr = (const float4*)&KVu[kj * VS_LD + cg * 32];
                #pragma unroll
                for (int c = 0; c < 8; c++) {
                    float4 v = vr[c];
                    acc[c * 4 + 0] += p * v.x;
                    acc[c * 4 + 1] += p * v.y;
                    acc[c * 4 + 2] += p * v.z;
                    acc[c * 4 + 3] += p * v.w;
                }
            }
        }
    }

    {
        const int q = tid & 63, cg = tid >> 6;
        float inv = 1.0f / l_s[q];
        float* Og = O + ((size_t)b * SS + q0 + q) * DIM + h * HD + cg * 32;
        #pragma unroll
        for (int c = 0; c < 8; c++) {
            float4 o = make_float4(acc[c*4+0]*inv, acc[c*4+1]*inv,
                                   acc[c*4+2]*inv, acc[c*4+3]*inv);
            ((float4*)Og)[c] = o;
        }
    }
}

// ---------------- launcher ---------------------------------------------------
extern "C" void kernel_launch(void* const* d_in, const int* in_sizes, int n_in,
                              void* d_out, int out_size)
{
    const float* x    = (const float*)d_in[0];
    const float* fcos = (const float*)d_in[1];
    const float* fsin = (const float*)d_in[2];
    const float* wq   = (const float*)d_in[3];
    const float* wk   = (const float*)d_in[4];
    const float* wv   = (const float*)d_in[5];
    const float* wo   = (const float*)d_in[6];
    float* out = (float*)d_out;

    float *pQ, *pK, *pV, *pA, *pxp, *pattp, *pwqp, *pwkp, *pwvp, *pwop;
    cudaGetSymbolAddress((void**)&pQ, g_Q);
    cudaGetSymbolAddress((void**)&pK, g_K);
    cudaGetSymbolAddress((void**)&pV, g_V);
    cudaGetSymbolAddress((void**)&pA, g_ATT);
    cudaGetSymbolAddress((void**)&pxp, g_xp);
    cudaGetSymbolAddress((void**)&pattp, g_attp);
    cudaGetSymbolAddress((void**)&pwqp, g_wqp);
    cudaGetSymbolAddress((void**)&pwkp, g_wkp);
    cudaGetSymbolAddress((void**)&pwvp, g_wvp);
    cudaGetSymbolAddress((void**)&pwop, g_wop);

    const size_t gsmem = GSTAGES * STAGE_BYTES + 1024;
    cudaFuncSetAttribute(gemm_mma, cudaFuncAttributeMaxDynamicSharedMemorySize, (int)gsmem);

    // pack weights / activations into fragment-major tf32 tiles
    pack_B<<<dim3(KTILES, DIM/128),      256>>>(wq, pwqp, DIM);
    pack_B<<<dim3(KTILES, (NKV*HD)/128), 256>>>(wk, pwkp, NKV*HD);
    pack_B<<<dim3(KTILES, (NKV*HD)/128), 256>>>(wv, pwvp, NKV*HD);
    pack_B<<<dim3(KTILES, DIM/128),      256>>>(wo, pwop, DIM);
    pack_A<<<dim3(KTILES, M_ROWS/128),   256>>>(x, pxp, DIM);

    // QKV projections (tensor cores, tf32)
    gemm_mma<<<dim3(DIM/128,      M_ROWS/128), 256, gsmem>>>(pxp, pwqp, pQ, DIM,    KTILES);
    gemm_mma<<<dim3((NKV*HD)/128, M_ROWS/128), 256, gsmem>>>(pxp, pwkp, pK, NKV*HD, KTILES);
    gemm_mma<<<dim3((NKV*HD)/128, M_ROWS/128), 256, gsmem>>>(pxp, pwvp, pV, NKV*HD, KTILES);

    // RoPE
    {
        int total = M_ROWS * (NH + NKV) * (HD / 2);
        rope_kernel<<<(total + 255) / 256, 256>>>(pQ, pK, fcos, fsin);
    }

    // attention (fp32 flash)
    {
        size_t smem = (size_t)(128 * QST_LD + KVU_FLOATS + 64 * SS_LD + 192) * sizeof(float);
        cudaFuncSetAttribute(attn_kernel, cudaFuncAttributeMaxDynamicSharedMemorySize, (int)smem);
        attn_kernel<<<dim3(SS/64, BB * NH), 256, smem>>>(pQ, pK, pV, pA);
    }

    // output projection
    pack_A<<<dim3(KTILES, M_ROWS/128), 256>>>(pA, pattp, DIM);
    gemm_mma<<<dim3(DIM/128, M_ROWS/128), 256, gsmem>>>(pattp, pwop, out, DIM, KTILES);
}

// round 4
// speedup vs baseline: 3.8579x; 1.8617x over previous
#include <cuda_runtime.h>
#include <cuda_bf16.h>
#include <cstdint>

// Problem constants
#define BB 2
#define SS 2048
#define DIM 2048
#define NH 16
#define NKV 8
#define HD 128
#define M_ROWS (BB*SS)          // 4096
#define KTILES 64               // K=2048 / 32

// ---------------- scratch (device globals: allocation-free) ----------------
__device__ float g_Q[(size_t)M_ROWS * DIM];
__device__ float g_K[(size_t)M_ROWS * (NKV*HD)];
__device__ float g_V[(size_t)M_ROWS * (NKV*HD)];
__device__ float g_ATT[(size_t)M_ROWS * DIM];
// packed bf16 hi/lo fragment-major buffers (1 float slot = 2 bf16)
__device__ float g_xp  [(size_t)M_ROWS * DIM];
__device__ float g_attp[(size_t)M_ROWS * DIM];
__device__ float g_wqp [(size_t)DIM * DIM];
__device__ float g_wkp [(size_t)DIM * (NKV*HD)];
__device__ float g_wvp [(size_t)DIM * (NKV*HD)];
__device__ float g_wop [(size_t)DIM * DIM];
// fragment-major tf32 tiles for attention
__device__ float g_Qr[(size_t)BB * NH  * 32 * 8192];   // 32MB
__device__ float g_Kr[(size_t)BB * NKV * 32 * 8192];   // 16MB
__device__ float g_Vr[(size_t)BB * NKV * 32 * 8192];   // 16MB

// ---------------- PTX helpers (base sm_90 / sm_80 features only!) -----------
__device__ __forceinline__ uint32_t smem_u32(const void* p) {
    uint32_t a;
    asm("{ .reg .u64 t; cvta.to.shared.u64 t, %1; cvt.u32.u64 %0, t; }" : "=r"(a) : "l"(p));
    return a;
}
__device__ __forceinline__ float tf32r(float x) {
    uint32_t u;
    asm("cvt.rna.tf32.f32 %0, %1;" : "=r"(u) : "f"(x));
    return __uint_as_float(u);
}

#define MBAR_INIT(a, cnt) \
    asm volatile("mbarrier.init.shared.b64 [%0], %1;" :: "r"(a), "r"(cnt) : "memory")
#define MBAR_EXPECT_TX(a, b) \
    asm volatile("mbarrier.arrive.expect_tx.shared.b64 _, [%0], %1;" :: "r"(a), "r"(b) : "memory")

__device__ __forceinline__ void mbar_wait(uint32_t addr, uint32_t phase) {
    uint32_t done;
    asm volatile(
        "{\n\t.reg .pred p;\n\t"
        "mbarrier.try_wait.parity.acquire.cta.shared::cta.b64 p, [%1], %2;\n\t"
        "selp.b32 %0, 1, 0, p;\n\t}"
        : "=r"(done) : "r"(addr), "r"(phase) : "memory");
    if (!done) {
        asm volatile(
            "{\n\t.reg .pred P1;\n\t"
            "W_%=:\n\t"
            "mbarrier.try_wait.parity.acquire.cta.shared::cta.b64 P1, [%0], %1, 0x989680;\n\t"
            "@P1 bra.uni D_%=;\n\t"
            "bra.uni W_%=;\n\t"
            "D_%=:\n\t}"
            :: "r"(addr), "r"(phase) : "memory");
    }
}
__device__ __forceinline__ void bulk_g2s(uint32_t dst, const void* src, uint32_t bytes, uint32_t mbar) {
    asm volatile(
        "cp.async.bulk.shared::cluster.global.mbarrier::complete_tx::bytes [%0], [%1], %2, [%3];"
        :: "r"(dst), "l"(src), "r"(bytes), "r"(mbar) : "memory");
}
__device__ __forceinline__ void fence_async() {
    asm volatile("fence.proxy.async;" ::: "memory");
}

// m16n8k8 tf32 mma
__device__ __forceinline__ void mma_tf32(float* c, const uint32_t* a, const uint32_t* b) {
    asm volatile(
        "mma.sync.aligned.m16n8k8.row.col.f32.tf32.tf32.f32 "
        "{%0,%1,%2,%3}, {%4,%5,%6,%7}, {%8,%9}, {%0,%1,%2,%3};"
        : "+f"(c[0]), "+f"(c[1]), "+f"(c[2]), "+f"(c[3])
        : "r"(a[0]), "r"(a[1]), "r"(a[2]), "r"(a[3]), "r"(b[0]), "r"(b[1]));
}
// m16n8k16 bf16 mma
__device__ __forceinline__ void mma_bf16(float* c, const uint32_t* a, const uint32_t* b) {
    asm volatile(
        "mma.sync.aligned.m16n8k16.row.col.f32.bf16.bf16.f32 "
        "{%0,%1,%2,%3}, {%4,%5,%6,%7}, {%8,%9}, {%0,%1,%2,%3};"
        : "+f"(c[0]), "+f"(c[1]), "+f"(c[2]), "+f"(c[3])
        : "r"(a[0]), "r"(a[1]), "r"(a[2]), "r"(a[3]), "r"(b[0]), "r"(b[1]));
}
#define LDS128(r, addr) \
    asm volatile("ld.shared.v4.b32 {%0,%1,%2,%3}, [%4];" \
        : "=r"((r)[0]), "=r"((r)[1]), "=r"((r)[2]), "=r"((r)[3]) : "r"(addr))
#define LDS64(r, addr) \
    asm volatile("ld.shared.v2.b32 {%0,%1}, [%2];" \
        : "=r"((r)[0]), "=r"((r)[1]) : "r"(addr))
#define LDS32(r, addr) \
    asm volatile("ld.shared.b32 %0, [%1];" : "=r"(r) : "r"(addr))
#define STS64F(addr, x, y) \
    asm volatile("st.shared.v2.f32 [%0], {%1,%2};" :: "r"(addr), "f"(x), "f"(y) : "memory")

// split fp32 pair into bf16-hi pair and bf16-lo (residual) pair, packed
__device__ __forceinline__ void split2(float x, float y, uint32_t& h, uint32_t& l) {
    __nv_bfloat16 hx = __float2bfloat16_rn(x);
    __nv_bfloat16 hy = __float2bfloat16_rn(y);
    float lx = x - __bfloat162float(hx);
    float ly = y - __bfloat162float(hy);
    __nv_bfloat162 hp = __halves2bfloat162(hx, hy);
    __nv_bfloat162 lp = __floats2bfloat162_rn(lx, ly);
    h = *reinterpret_cast<uint32_t*>(&hp);
    l = *reinterpret_cast<uint32_t*>(&lp);
}

// ---------------- pack A: [M,K] fp32 -> bf16 hi/lo fragment-major tiles ------
// Tile (mt128, kc32): uint4 slots [ks2(2)][mtg(8)][hl(2)][lane(32)], 16KB.
__global__ __launch_bounds__(256) void pack_A_bf16(const float* __restrict__ src,
                                                   float* __restrict__ dst, int K)
{
    const int kc = blockIdx.x, mt = blockIdx.y;
    const int tid = threadIdx.x;
    uint4* tb = (uint4*)(dst + (size_t)(mt * (K / 32) + kc) * 4096);
    #pragma unroll
    for (int t = 0; t < 2; t++) {
        int u = tid + 256 * t;
        int ks2 = u >> 8, mtg = (u >> 5) & 7, lane = u & 31;
        int m = mt * 128 + mtg * 16 + (lane >> 2);
        int k = kc * 32 + ks2 * 16 + (lane & 3) * 2;
        const float* p0 = src + (size_t)m * K + k;
        const float* p1 = p0 + 8 * (size_t)K;
        float2 v00 = *(const float2*)p0;
        float2 v01 = *(const float2*)(p0 + 8);
        float2 v10 = *(const float2*)p1;
        float2 v11 = *(const float2*)(p1 + 8);
        uint32_t h0,h1,h2,h3,l0,l1,l2,l3;
        split2(v00.x, v00.y, h0, l0);
        split2(v10.x, v10.y, h1, l1);
        split2(v01.x, v01.y, h2, l2);
        split2(v11.x, v11.y, h3, l3);
        int bi = ((ks2 * 8 + mtg) * 2) * 32 + lane;
        tb[bi]      = make_uint4(h0, h1, h2, h3);
        tb[bi + 32] = make_uint4(l0, l1, l2, l3);
    }
}

// ---------------- pack B: w[K,N] -> bf16 hi/lo fragment-major tiles ----------
// Tile (nt128, kc32): uint2 slots [ks2(2)][ntg(16)][hl(2)][lane(32)], 16KB.
__global__ __launch_bounds__(256) void pack_B_bf16(const float* __restrict__ w,
                                                   float* __restrict__ dst, int N)
{
    const int kc = blockIdx.x, nt = blockIdx.y;
    const int tid = threadIdx.x;
    uint2* tb = (uint2*)(dst + (size_t)(nt * KTILES + kc) * 4096);
    #pragma unroll
    for (int t = 0; t < 4; t++) {
        int u = tid + 256 * t;
        int ks2 = u >> 9, ntg = (u >> 5) & 15, lane = u & 31;
        int k = kc * 32 + ks2 * 16 + (lane & 3) * 2;
        int n = nt * 128 + ntg * 8 + (lane >> 2);
        float w0 = w[(size_t)k * N + n];
        float w1 = w[(size_t)(k + 1) * N + n];
        float w2 = w[(size_t)(k + 8) * N + n];
        float w3 = w[(size_t)(k + 9) * N + n];
        uint32_t bh0, bl0, bh1, bl1;
        split2(w0, w1, bh0, bl0);
        split2(w2, w3, bh1, bl1);
        int bi = ((ks2 * 16 + ntg) * 2) * 32 + lane;
        tb[bi]      = make_uint2(bh0, bh1);
        tb[bi + 32] = make_uint2(bl0, bl1);
    }
}

// ---------------- bf16x3 GEMM: C[M,N] = A*B (fp32-accurate) ------------------
#define GSTAGES 3
#define STAGE_BYTES 32768   // A 16KB + B 16KB

__global__ __launch_bounds__(256) void gemm_mma(
    const float* __restrict__ Ap, const float* __restrict__ Bp,
    float* __restrict__ C, int Ndim, int kTiles)
{
    extern __shared__ float dyn[];
    __shared__ __align__(8) uint64_t mbar[GSTAGES];

    const int tid  = threadIdx.x;
    const int lane = tid & 31;
    const int warp = tid >> 5;
    const int wm = warp >> 2;
    const int wn = warp & 3;
    const int nt = blockIdx.x, mt = blockIdx.y;

    uint32_t sbase = (smem_u32(dyn) + 1023) & ~1023u;
    uint32_t mb = smem_u32(mbar);
    #define FULLB(s) (mb + (s) * 8)

    if (tid == 0) {
        #pragma unroll
        for (int s = 0; s < GSTAGES; s++) MBAR_INIT(FULLB(s), 1);
    }
    __syncthreads();

    const char* At = (const char*)(Ap + (size_t)mt * kTiles * 4096);
    const char* Bt = (const char*)(Bp + (size_t)nt * kTiles * 4096);

    if (tid == 0) {
        fence_async();
        #pragma unroll
        for (int j = 0; j < GSTAGES; j++) {
            MBAR_EXPECT_TX(FULLB(j), STAGE_BYTES);
            bulk_g2s(sbase + j * STAGE_BYTES,         At + (size_t)j * 16384, 16384, FULLB(j));
            bulk_g2s(sbase + j * STAGE_BYTES + 16384, Bt + (size_t)j * 16384, 16384, FULLB(j));
        }
    }

    float acc[4][4][4];
    #pragma unroll
    for (int i = 0; i < 4; i++)
        #pragma unroll
        for (int j = 0; j < 4; j++)
            #pragma unroll
            for (int q = 0; q < 4; q++) acc[i][j][q] = 0.f;

    for (int i = 0; i < kTiles; i++) {
        const int s = i % GSTAGES;
        const uint32_t ph = (i / GSTAGES) & 1;
        mbar_wait(FULLB(s), ph);
        const uint32_t a_base = sbase + s * STAGE_BYTES;
        const uint32_t b_base = a_base + 16384;

        #pragma unroll
        for (int ks = 0; ks < 2; ks++) {
            uint32_t ah[4][4], al[4][4], bh[4][2], bl[4][2];
            #pragma unroll
            for (int ii = 0; ii < 4; ii++) {
                LDS128(ah[ii], a_base + (uint32_t)((((ks * 8 + wm * 4 + ii) * 2 + 0) * 32 + lane) * 16));
                LDS128(al[ii], a_base + (uint32_t)((((ks * 8 + wm * 4 + ii) * 2 + 1) * 32 + lane) * 16));
            }
            #pragma unroll
            for (int jj = 0; jj < 4; jj++) {
                LDS64(bh[jj], b_base + (uint32_t)((((ks * 16 + wn * 4 + jj) * 2 + 0) * 32 + lane) * 8));
                LDS64(bl[jj], b_base + (uint32_t)((((ks * 16 + wn * 4 + jj) * 2 + 1) * 32 + lane) * 8));
            }
            #pragma unroll
            for (int ii = 0; ii < 4; ii++)
                #pragma unroll
                for (int jj = 0; jj < 4; jj++) {
                    mma_bf16(acc[ii][jj], ah[ii], bh[jj]);
                    mma_bf16(acc[ii][jj], ah[ii], bl[jj]);
                    mma_bf16(acc[ii][jj], al[ii], bh[jj]);
                }
        }
        __syncthreads();
        if (tid == 0) {
            int jn = i + GSTAGES;
            if (jn < kTiles) {
                fence_async();
                MBAR_EXPECT_TX(FULLB(s), STAGE_BYTES);
                bulk_g2s(a_base, At + (size_t)jn * 16384, 16384, FULLB(s));
                bulk_g2s(b_base, Bt + (size_t)jn * 16384, 16384, FULLB(s));
            }
        }
    }

    const int r = lane >> 2, cc = lane & 3;
    #pragma unroll
    for (int ii = 0; ii < 4; ii++) {
        int m0 = mt * 128 + wm * 64 + ii * 16 + r;
        float* row0 = C + (size_t)m0 * Ndim + nt * 128 + wn * 32 + 2 * cc;
        float* row1 = row0 + 8 * (size_t)Ndim;
        #pragma unroll
        for (int jj = 0; jj < 4; jj++) {
            *(float2*)(row0 + jj * 8) = make_float2(acc[ii][jj][0], acc[ii][jj][1]);
            *(float2*)(row1 + jj * 8) = make_float2(acc[ii][jj][2], acc[ii][jj][3]);
        }
    }
}

// ---------------- RoPE (in-place on g_Q and g_K) ----------------------------
__global__ void rope_kernel(float* __restrict__ Q, float* __restrict__ Kt,
                            const float* __restrict__ cosp,
                            const float* __restrict__ sinp)
{
    const int totalQ = M_ROWS * NH * (HD / 2);
    const int totalK = M_ROWS * NKV * (HD / 2);
    int i = blockIdx.x * blockDim.x + threadIdx.x;
    if (i < totalQ) {
        int j  = i & 63;
        int h  = (i >> 6) & (NH - 1);
        int bs = i >> 10;
        int s  = bs & (SS - 1);
        float c  = cosp[s * 64 + j];
        float sn = sinp[s * 64 + j];
        float* p = Q + (size_t)bs * DIM + h * HD + 2 * j;
        float p1 = p[0], p2 = p[1];
        p[0] = p1 * c - p2 * sn;
        p[1] = p1 * sn + p2 * c;
    } else {
        i -= totalQ;
        if (i >= totalK) return;
        int j  = i & 63;
        int h  = (i >> 6) & (NKV - 1);
        int bs = i >> 9;
        int s  = bs & (SS - 1);
        float c  = cosp[s * 64 + j];
        float sn = sinp[s * 64 + j];
        float* p = Kt + (size_t)bs * (NKV * HD) + h * HD + 2 * j;
        float p1 = p[0], p2 = p[1];
        p[0] = p1 * c - p2 * sn;
        p[1] = p1 * sn + p2 * c;
    }
}

// ---------------- repack Q/K/V into tf32 fragment-major tiles ----------------
// Q tile (b,h,qt): [mtg(4)][kstep(16)][lane(32)] x float4; scale folded in.
__global__ __launch_bounds__(256) void qrep(const float* __restrict__ Q, float* __restrict__ dst)
{
    const int qt = blockIdx.x, bh = blockIdx.y;
    const int b = bh >> 4, h = bh & 15;
    const int tid = threadIdx.x;
    const float scale = 0.08838834764831845f;
    float4* out = (float4*)(dst + ((size_t)bh * 32 + qt) * 8192);
    #pragma unroll
    for (int t = 0; t < 8; t++) {
        int u = tid + 256 * t;
        int mtg = u >> 9, ks = (u >> 5) & 15, lane = u & 31;
        int row = b * SS + qt * 64 + mtg * 16 + (lane >> 2);
        int col = h * HD + ks * 8 + (lane & 3);
        const float* p = Q + (size_t)row * DIM + col;
        out[u] = make_float4(tf32r(p[0] * scale), tf32r(p[8 * DIM] * scale),
                             tf32r(p[4] * scale), tf32r(p[8 * DIM + 4] * scale));
    }
}
// K tile (b,hk,kvt): B-frag [dstep(16)][kvg(8)][lane(32)] x float2
__global__ __launch_bounds__(256) void krep(const float* __restrict__ K, float* __restrict__ dst)
{
    const int kvt = blockIdx.x, bhk = blockIdx.y;
    const int b = bhk >> 3, hk = bhk & 7;
    const int tid = threadIdx.x;
    float2* out = (float2*)(dst + ((size_t)bhk * 32 + kvt) * 8192);
    #pragma unroll
    for (int t = 0; t < 16; t++) {
        int u = tid + 256 * t;
        int ds = u >> 8, kvg = (u >> 5) & 7, lane = u & 31;
        int kv = kvt * 64 + kvg * 8 + (lane >> 2);
        int d  = ds * 8 + (lane & 3);
        const float* p = K + (size_t)(b * SS + kv) * (NKV * HD) + hk * HD + d;
        out[u] = make_float2(tf32r(p[0]), tf32r(p[4]));
    }
}
// V tile (b,hk,kvt): B-frag [ks(8)][ng(16)][lane(32)] x float2
__global__ __launch_bounds__(256) void vrep(const float* __restrict__ V, float* __restrict__ dst)
{
    const int kvt = blockIdx.x, bhk = blockIdx.y;
    const int b = bhk >> 3, hk = bhk & 7;
    const int tid = threadIdx.x;
    float2* out = (float2*)(dst + ((size_t)bhk * 32 + kvt) * 8192);
    #pragma unroll
    for (int t = 0; t < 16; t++) {
        int u = tid + 256 * t;
        int ks = u >> 9, ng = (u >> 5) & 15, lane = u & 31;
        int kv = kvt * 64 + ks * 8 + (lane & 3);
        int d  = ng * 8 + (lane >> 2);
        const float* p = V + (size_t)(b * SS + kv) * (NKV * HD) + hk * HD + d;
        out[u] = make_float2(tf32r(p[0]), tf32r(p[4 * NKV * HD]));
    }
}

// ---------------- tensor-core flash attention (tf32) ------------------------
// BQ=64, BKV=64, 4 warps, 2-stage KV bulk ring. Q frags in smem, P via smem.
#define ATTN_SMEM (32768 + 2*65536 + 64*68*4)   // Q + 2 stages + P = 181248

__global__ __launch_bounds__(128) void attn_mma(
    const float* __restrict__ Qr, const float* __restrict__ Kr,
    const float* __restrict__ Vr, float* __restrict__ O)
{
    extern __shared__ float sm[];
    __shared__ __align__(8) uint64_t bars[3];

    const int tid = threadIdx.x;
    const int lane = tid & 31, wq = tid >> 5;
    const int qt = blockIdx.x, bh = blockIdx.y;
    const int b = bh >> 4, h = bh & 15;
    const int bhk = b * 8 + (h >> 1);
    const int niter = qt + 1;

    uint32_t sbase = smem_u32(sm);
    uint32_t qs  = sbase;
    uint32_t st0 = sbase + 32768;
    uint32_t ps  = sbase + 32768 + 131072;
    uint32_t mb  = smem_u32(bars);

    if (tid == 0) {
        MBAR_INIT(mb, 1); MBAR_INIT(mb + 8, 1); MBAR_INIT(mb + 16, 1);
    }
    __syncthreads();
    if (tid == 0) {
        fence_async();
        MBAR_EXPECT_TX(mb + 16, 32768);
        bulk_g2s(qs, Qr + ((size_t)bh * 32 + qt) * 8192, 32768, mb + 16);
        int np = niter < 2 ? niter : 2;
        for (int j = 0; j < np; j++) {
            MBAR_EXPECT_TX(mb + j * 8, 65536);
            bulk_g2s(st0 + j * 65536,         Kr + ((size_t)bhk * 32 + j) * 8192, 32768, mb + j * 8);
            bulk_g2s(st0 + j * 65536 + 32768, Vr + ((size_t)bhk * 32 + j) * 8192, 32768, mb + j * 8);
        }
    }

    float o[16][4];
    #pragma unroll
    for (int i = 0; i < 16; i++)
        #pragma unroll
        for (int q = 0; q < 4; q++) o[i][q] = 0.f;
    float mr0 = -1e30f, mr1 = -1e30f, lr0 = 0.f, lr1 = 0.f;
    const int r0 = lane >> 2;
    const int c0 = (lane & 3) * 2;

    mbar_wait(mb + 16, 0);

    for (int kb = 0; kb < niter; kb++) {
        const int s = kb & 1;
        mbar_wait(mb + s * 8, (kb >> 1) & 1);
        const uint32_t kbase = st0 + s * 65536;
        const uint32_t vbase = kbase + 32768;

        // QK^T: S[16][64] per warp
        float sc[8][4];
        #pragma unroll
        for (int ng = 0; ng < 8; ng++)
            #pragma unroll
            for (int q = 0; q < 4; q++) sc[ng][q] = 0.f;
        #pragma unroll
        for (int ks = 0; ks < 16; ks++) {
            uint32_t qf[4];
            LDS128(qf, qs + (uint32_t)(((wq * 16 + ks) * 32 + lane) * 16));
            #pragma unroll
            for (int ng = 0; ng < 8; ng++) {
                uint32_t kf[2];
                LDS64(kf, kbase + (uint32_t)(((ks * 8 + ng) * 32 + lane) * 8));
                mma_tf32(sc[ng], qf, kf);
            }
        }
        // causal mask on diagonal tile
        if (kb == qt) {
            const int rowA = wq * 16 + r0;
            #pragma unroll
            for (int ng = 0; ng < 8; ng++) {
                int col = ng * 8 + c0;
                if (col     > rowA)     sc[ng][0] = -1e30f;
                if (col + 1 > rowA)     sc[ng][1] = -1e30f;
                if (col     > rowA + 8) sc[ng][2] = -1e30f;
                if (col + 1 > rowA + 8) sc[ng][3] = -1e30f;
            }
        }
        // online softmax (rows r0 and r0+8)
        float mA = -1e30f, mB = -1e30f;
        #pragma unroll
        for (int ng = 0; ng < 8; ng++) {
            mA = fmaxf(mA, fmaxf(sc[ng][0], sc[ng][1]));
            mB = fmaxf(mB, fmaxf(sc[ng][2], sc[ng][3]));
        }
        mA = fmaxf(mA, __shfl_xor_sync(0xffffffffu, mA, 1));
        mA = fmaxf(mA, __shfl_xor_sync(0xffffffffu, mA, 2));
        mB = fmaxf(mB, __shfl_xor_sync(0xffffffffu, mB, 1));
        mB = fmaxf(mB, __shfl_xor_sync(0xffffffffu, mB, 2));
        float mnA = fmaxf(mr0, mA), mnB = fmaxf(mr1, mB);
        float fA = __expf(mr0 - mnA), fB = __expf(mr1 - mnB);
        mr0 = mnA; mr1 = mnB;
        float sA = 0.f, sB = 0.f;
        const uint32_t prowA = ps + (uint32_t)(((wq * 16 + r0) * 68 + c0) * 4);
        const uint32_t prowB = prowA + 8 * 68 * 4;
        #pragma unroll
        for (int ng = 0; ng < 8; ng++) {
            float p0 = __expf(sc[ng][0] - mnA);
            float p1 = __expf(sc[ng][1] - mnA);
            float p2 = __expf(sc[ng][2] - mnB);
            float p3 = __expf(sc[ng][3] - mnB);
            sA += p0 + p1; sB += p2 + p3;
            STS64F(prowA + ng * 32, tf32r(p0), tf32r(p1));
            STS64F(prowB + ng * 32, tf32r(p2), tf32r(p3));
        }
        sA += __shfl_xor_sync(0xffffffffu, sA, 1);
        sA += __shfl_xor_sync(0xffffffffu, sA, 2);
        sB += __shfl_xor_sync(0xffffffffu, sB, 1);
        sB += __shfl_xor_sync(0xffffffffu, sB, 2);
        lr0 = lr0 * fA + sA;
        lr1 = lr1 * fB + sB;
        #pragma unroll
        for (int ng = 0; ng < 16; ng++) {
            o[ng][0] *= fA; o[ng][1] *= fA;
            o[ng][2] *= fB; o[ng][3] *= fB;
        }
        __syncwarp();
        // PV: O[16][128] += P[16][64] * V[64][128]
        #pragma unroll
        for (int ks = 0; ks < 8; ks++) {
            uint32_t pf[4];
            uint32_t pa = ps + (uint32_t)(((wq * 16 + r0) * 68 + ks * 8 + (lane & 3)) * 4);
            LDS32(pf[0], pa);
            LDS32(pf[1], pa + 8 * 68 * 4);
            LDS32(pf[2], pa + 16);
            LDS32(pf[3], pa + 8 * 68 * 4 + 16);
            #pragma unroll
            for (int ng = 0; ng < 16; ng++) {
                uint32_t vf[2];
                LDS64(vf, vbase + (uint32_t)(((ks * 16 + ng) * 32 + lane) * 8));
                mma_tf32(o[ng], pf, vf);
            }
        }
        __syncthreads();
        if (tid == 0 && kb + 2 < niter) {
            int j = kb + 2;
            MBAR_EXPECT_TX(mb + s * 8, 65536);
            bulk_g2s(kbase, Kr + ((size_t)bhk * 32 + j) * 8192, 32768, mb + s * 8);
            bulk_g2s(vbase, Vr + ((size_t)bhk * 32 + j) * 8192, 32768, mb + s * 8);
        }
    }

    // epilogue
    float iA = 1.0f / lr0, iB = 1.0f / lr1;
    int rowA = qt * 64 + wq * 16 + r0;
    float* pA = O + ((size_t)(b * SS + rowA)) * DIM + h * HD + c0;
    float* pB = pA + 8 * (size_t)DIM;
    #pragma unroll
    for (int ng = 0; ng < 16; ng++) {
        *(float2*)(pA + ng * 8) = make_float2(o[ng][0] * iA, o[ng][1] * iA);
        *(float2*)(pB + ng * 8) = make_float2(o[ng][2] * iB, o[ng][3] * iB);
    }
}

// ---------------- launcher ---------------------------------------------------
extern "C" void kernel_launch(void* const* d_in, const int* in_sizes, int n_in,
                              void* d_out, int out_size)
{
    const float* x    = (const float*)d_in[0];
    const float* fcos = (const float*)d_in[1];
    const float* fsin = (const float*)d_in[2];
    const float* wq   = (const float*)d_in[3];
    const float* wk   = (const float*)d_in[4];
    const float* wv   = (const float*)d_in[5];
    const float* wo   = (const float*)d_in[6];
    float* out = (float*)d_out;

    float *pQ, *pK, *pV, *pA, *pxp, *pattp, *pwqp, *pwkp, *pwvp, *pwop, *pQr, *pKr, *pVr;
    cudaGetSymbolAddress((void**)&pQ, g_Q);
    cudaGetSymbolAddress((void**)&pK, g_K);
    cudaGetSymbolAddress((void**)&pV, g_V);
    cudaGetSymbolAddress((void**)&pA, g_ATT);
    cudaGetSymbolAddress((void**)&pxp, g_xp);
    cudaGetSymbolAddress((void**)&pattp, g_attp);
    cudaGetSymbolAddress((void**)&pwqp, g_wqp);
    cudaGetSymbolAddress((void**)&pwkp, g_wkp);
    cudaGetSymbolAddress((void**)&pwvp, g_wvp);
    cudaGetSymbolAddress((void**)&pwop, g_wop);
    cudaGetSymbolAddress((void**)&pQr, g_Qr);
    cudaGetSymbolAddress((void**)&pKr, g_Kr);
    cudaGetSymbolAddress((void**)&pVr, g_Vr);

    const size_t gsmem = GSTAGES * STAGE_BYTES + 1024;
    cudaFuncSetAttribute(gemm_mma, cudaFuncAttributeMaxDynamicSharedMemorySize, (int)gsmem);
    cudaFuncSetAttribute(attn_mma, cudaFuncAttributeMaxDynamicSharedMemorySize, ATTN_SMEM);

    // pack weights / activations into bf16 hi/lo fragment-major tiles
    pack_B_bf16<<<dim3(KTILES, DIM/128),      256>>>(wq, pwqp, DIM);
    pack_B_bf16<<<dim3(KTILES, (NKV*HD)/128), 256>>>(wk, pwkp, NKV*HD);
    pack_B_bf16<<<dim3(KTILES, (NKV*HD)/128), 256>>>(wv, pwvp, NKV*HD);
    pack_B_bf16<<<dim3(KTILES, DIM/128),      256>>>(wo, pwop, DIM);
    pack_A_bf16<<<dim3(KTILES, M_ROWS/128),   256>>>(x, pxp, DIM);

    // QKV projections (bf16x3 tensor cores)
    gemm_mma<<<dim3(DIM/128,      M_ROWS/128), 256, gsmem>>>(pxp, pwqp, pQ, DIM,    KTILES);
    gemm_mma<<<dim3((NKV*HD)/128, M_ROWS/128), 256, gsmem>>>(pxp, pwkp, pK, NKV*HD, KTILES);
    gemm_mma<<<dim3((NKV*HD)/128, M_ROWS/128), 256, gsmem>>>(pxp, pwvp, pV, NKV*HD, KTILES);

    // RoPE
    {
        int total = M_ROWS * (NH + NKV) * (HD / 2);
        rope_kernel<<<(total + 255) / 256, 256>>>(pQ, pK, fcos, fsin);
    }

    // repack Q/K/V into fragment-major tf32 tiles
    qrep<<<dim3(32, BB * NH),  256>>>(pQ, pQr);
    krep<<<dim3(32, BB * NKV), 256>>>(pK, pKr);
    vrep<<<dim3(32, BB * NKV), 256>>>(pV, pVr);

    // tensor-core flash attention
    attn_mma<<<dim3(32, BB * NH), 128, ATTN_SMEM>>>(pQr, pKr, pVr, pA);

    // output projection (bf16x3)
    pack_A_bf16<<<dim3(KTILES, M_ROWS/128), 256>>>(pA, pattp, DIM);
    gemm_mma<<<dim3(DIM/128, M_ROWS/128), 256, gsmem>>>(pattp, pwop, out, DIM, KTILES);
}

// round 5
// speedup vs baseline: 3.9192x; 1.0159x over previous
#include <cuda_runtime.h>
#include <cuda_bf16.h>
#include <cstdint>

// Problem constants
#define BB 2
#define SS 2048
#define DIM 2048
#define NH 16
#define NKV 8
#define HD 128
#define M_ROWS (BB*SS)          // 4096
#define KTILES 64               // K=2048 / 32

// ---------------- scratch (device globals: allocation-free) ----------------
__device__ float g_Q[(size_t)M_ROWS * DIM];
__device__ float g_K[(size_t)M_ROWS * (NKV*HD)];
__device__ float g_V[(size_t)M_ROWS * (NKV*HD)];
// packed bf16 hi/lo fragment-major buffers
__device__ float g_xp  [(size_t)M_ROWS * DIM];
__device__ float g_attp[(size_t)M_ROWS * DIM];
__device__ float g_wqp [(size_t)DIM * DIM];
__device__ float g_wkp [(size_t)DIM * (NKV*HD)];
__device__ float g_wvp [(size_t)DIM * (NKV*HD)];
__device__ float g_wop [(size_t)DIM * DIM];
// fragment-major tiles for attention
__device__ float g_Qr[(size_t)BB * NH  * 32 * 8192];   // tf32 frags
__device__ float g_Kr[(size_t)BB * NKV * 32 * 8192];   // tf32 frags
__device__ float g_Vr[(size_t)BB * NKV * 32 * 8192];   // bf16 hi/lo frags

// ---------------- PTX helpers (base sm_90 / sm_80 features only!) -----------
__device__ __forceinline__ uint32_t smem_u32(const void* p) {
    uint32_t a;
    asm("{ .reg .u64 t; cvta.to.shared.u64 t, %1; cvt.u32.u64 %0, t; }" : "=r"(a) : "l"(p));
    return a;
}
__device__ __forceinline__ float tf32r(float x) {
    uint32_t u;
    asm("cvt.rna.tf32.f32 %0, %1;" : "=r"(u) : "f"(x));
    return __uint_as_float(u);
}

#define MBAR_INIT(a, cnt) \
    asm volatile("mbarrier.init.shared.b64 [%0], %1;" :: "r"(a), "r"(cnt) : "memory")
#define MBAR_EXPECT_TX(a, b) \
    asm volatile("mbarrier.arrive.expect_tx.shared.b64 _, [%0], %1;" :: "r"(a), "r"(b) : "memory")

__device__ __forceinline__ void mbar_wait(uint32_t addr, uint32_t phase) {
    uint32_t done;
    asm volatile(
        "{\n\t.reg .pred p;\n\t"
        "mbarrier.try_wait.parity.acquire.cta.shared::cta.b64 p, [%1], %2;\n\t"
        "selp.b32 %0, 1, 0, p;\n\t}"
        : "=r"(done) : "r"(addr), "r"(phase) : "memory");
    if (!done) {
        asm volatile(
            "{\n\t.reg .pred P1;\n\t"
            "W_%=:\n\t"
            "mbarrier.try_wait.parity.acquire.cta.shared::cta.b64 P1, [%0], %1, 0x989680;\n\t"
            "@P1 bra.uni D_%=;\n\t"
            "bra.uni W_%=;\n\t"
            "D_%=:\n\t}"
            :: "r"(addr), "r"(phase) : "memory");
    }
}
__device__ __forceinline__ void bulk_g2s(uint32_t dst, const void* src, uint32_t bytes, uint32_t mbar) {
    asm volatile(
        "cp.async.bulk.shared::cluster.global.mbarrier::complete_tx::bytes [%0], [%1], %2, [%3];"
        :: "r"(dst), "l"(src), "r"(bytes), "r"(mbar) : "memory");
}
__device__ __forceinline__ void fence_async() {
    asm volatile("fence.proxy.async;" ::: "memory");
}

__device__ __forceinline__ void mma_tf32(float* c, const uint32_t* a, const uint32_t* b) {
    asm volatile(
        "mma.sync.aligned.m16n8k8.row.col.f32.tf32.tf32.f32 "
        "{%0,%1,%2,%3}, {%4,%5,%6,%7}, {%8,%9}, {%0,%1,%2,%3};"
        : "+f"(c[0]), "+f"(c[1]), "+f"(c[2]), "+f"(c[3])
        : "r"(a[0]), "r"(a[1]), "r"(a[2]), "r"(a[3]), "r"(b[0]), "r"(b[1]));
}
__device__ __forceinline__ void mma_bf16(float* c, const uint32_t* a, const uint32_t* b) {
    asm volatile(
        "mma.sync.aligned.m16n8k16.row.col.f32.bf16.bf16.f32 "
        "{%0,%1,%2,%3}, {%4,%5,%6,%7}, {%8,%9}, {%0,%1,%2,%3};"
        : "+f"(c[0]), "+f"(c[1]), "+f"(c[2]), "+f"(c[3])
        : "r"(a[0]), "r"(a[1]), "r"(a[2]), "r"(a[3]), "r"(b[0]), "r"(b[1]));
}
#define LDS128(r, addr) \
    asm volatile("ld.shared.v4.b32 {%0,%1,%2,%3}, [%4];" \
        : "=r"((r)[0]), "=r"((r)[1]), "=r"((r)[2]), "=r"((r)[3]) : "r"(addr))
#define LDS64(r, addr) \
    asm volatile("ld.shared.v2.b32 {%0,%1}, [%2];" \
        : "=r"((r)[0]), "=r"((r)[1]) : "r"(addr))

// split fp32 pair into bf16-hi pair and bf16-lo (residual) pair, packed
__device__ __forceinline__ void split2(float x, float y, uint32_t& h, uint32_t& l) {
    __nv_bfloat16 hx = __float2bfloat16_rn(x);
    __nv_bfloat16 hy = __float2bfloat16_rn(y);
    float lx = x - __bfloat162float(hx);
    float ly = y - __bfloat162float(hy);
    __nv_bfloat162 hp = __halves2bfloat162(hx, hy);
    __nv_bfloat162 lp = __floats2bfloat162_rn(lx, ly);
    h = *reinterpret_cast<uint32_t*>(&hp);
    l = *reinterpret_cast<uint32_t*>(&lp);
}
__device__ __forceinline__ uint32_t packbf(float x, float y) {
    __nv_bfloat162 hp = __floats2bfloat162_rn(x, y);
    return *reinterpret_cast<uint32_t*>(&hp);
}

// ---------------- pack A: [M,K] fp32 -> bf16 hi/lo fragment-major tiles ------
__global__ __launch_bounds__(256) void pack_A_bf16(const float* __restrict__ src,
                                                   float* __restrict__ dst, int K)
{
    const int kc = blockIdx.x, mt = blockIdx.y;
    const int tid = threadIdx.x;
    uint4* tb = (uint4*)(dst + (size_t)(mt * (K / 32) + kc) * 4096);
    #pragma unroll
    for (int t = 0; t < 2; t++) {
        int u = tid + 256 * t;
        int ks2 = u >> 8, mtg = (u >> 5) & 7, lane = u & 31;
        int m = mt * 128 + mtg * 16 + (lane >> 2);
        int k = kc * 32 + ks2 * 16 + (lane & 3) * 2;
        const float* p0 = src + (size_t)m * K + k;
        const float* p1 = p0 + 8 * (size_t)K;
        float2 v00 = *(const float2*)p0;
        float2 v01 = *(const float2*)(p0 + 8);
        float2 v10 = *(const float2*)p1;
        float2 v11 = *(const float2*)(p1 + 8);
        uint32_t h0,h1,h2,h3,l0,l1,l2,l3;
        split2(v00.x, v00.y, h0, l0);
        split2(v10.x, v10.y, h1, l1);
        split2(v01.x, v01.y, h2, l2);
        split2(v11.x, v11.y, h3, l3);
        int bi = ((ks2 * 8 + mtg) * 2) * 32 + lane;
        tb[bi]      = make_uint4(h0, h1, h2, h3);
        tb[bi + 32] = make_uint4(l0, l1, l2, l3);
    }
}

// ---------------- pack B: w[K,N] -> bf16 hi/lo fragment-major tiles ----------
__global__ __launch_bounds__(256) void pack_B_bf16(const float* __restrict__ w,
                                                   float* __restrict__ dst, int N)
{
    const int kc = blockIdx.x, nt = blockIdx.y;
    const int tid = threadIdx.x;
    uint2* tb = (uint2*)(dst + (size_t)(nt * KTILES + kc) * 4096);
    #pragma unroll
    for (int t = 0; t < 4; t++) {
        int u = tid + 256 * t;
        int ks2 = u >> 9, ntg = (u >> 5) & 15, lane = u & 31;
        int k = kc * 32 + ks2 * 16 + (lane & 3) * 2;
        int n = nt * 128 + ntg * 8 + (lane >> 2);
        float w0 = w[(size_t)k * N + n];
        float w1 = w[(size_t)(k + 1) * N + n];
        float w2 = w[(size_t)(k + 8) * N + n];
        float w3 = w[(size_t)(k + 9) * N + n];
        uint32_t bh0, bl0, bh1, bl1;
        split2(w0, w1, bh0, bl0);
        split2(w2, w3, bh1, bl1);
        int bi = ((ks2 * 16 + ntg) * 2) * 32 + lane;
        tb[bi]      = make_uint2(bh0, bh1);
        tb[bi + 32] = make_uint2(bl0, bl1);
    }
}

// ---------------- bf16x3 GEMM: C[M,N] = A*B (fp32-accurate) ------------------
#define GSTAGES 3
#define STAGE_BYTES 32768

__global__ __launch_bounds__(256) void gemm_mma(
    const float* __restrict__ Ap, const float* __restrict__ Bp,
    float* __restrict__ C, int Ndim, int kTiles)
{
    extern __shared__ float dyn[];
    __shared__ __align__(8) uint64_t mbar[GSTAGES];

    const int tid  = threadIdx.x;
    const int lane = tid & 31;
    const int warp = tid >> 5;
    const int wm = warp >> 2;
    const int wn = warp & 3;
    const int nt = blockIdx.x, mt = blockIdx.y;

    uint32_t sbase = (smem_u32(dyn) + 1023) & ~1023u;
    uint32_t mb = smem_u32(mbar);
    #define FULLB(s) (mb + (s) * 8)

    if (tid == 0) {
        #pragma unroll
        for (int s = 0; s < GSTAGES; s++) MBAR_INIT(FULLB(s), 1);
    }
    __syncthreads();

    const char* At = (const char*)(Ap + (size_t)mt * kTiles * 4096);
    const char* Bt = (const char*)(Bp + (size_t)nt * kTiles * 4096);

    if (tid == 0) {
        fence_async();
        #pragma unroll
        for (int j = 0; j < GSTAGES; j++) {
            MBAR_EXPECT_TX(FULLB(j), STAGE_BYTES);
            bulk_g2s(sbase + j * STAGE_BYTES,         At + (size_t)j * 16384, 16384, FULLB(j));
            bulk_g2s(sbase + j * STAGE_BYTES + 16384, Bt + (size_t)j * 16384, 16384, FULLB(j));
        }
    }

    float acc[4][4][4];
    #pragma unroll
    for (int i = 0; i < 4; i++)
        #pragma unroll
        for (int j = 0; j < 4; j++)
            #pragma unroll
            for (int q = 0; q < 4; q++) acc[i][j][q] = 0.f;

    for (int i = 0; i < kTiles; i++) {
        const int s = i % GSTAGES;
        const uint32_t ph = (i / GSTAGES) & 1;
        mbar_wait(FULLB(s), ph);
        const uint32_t a_base = sbase + s * STAGE_BYTES;
        const uint32_t b_base = a_base + 16384;

        #pragma unroll
        for (int ks = 0; ks < 2; ks++) {
            uint32_t ah[4][4], al[4][4], bh[4][2], bl[4][2];
            #pragma unroll
            for (int ii = 0; ii < 4; ii++) {
                LDS128(ah[ii], a_base + (uint32_t)((((ks * 8 + wm * 4 + ii) * 2 + 0) * 32 + lane) * 16));
                LDS128(al[ii], a_base + (uint32_t)((((ks * 8 + wm * 4 + ii) * 2 + 1) * 32 + lane) * 16));
            }
            #pragma unroll
            for (int jj = 0; jj < 4; jj++) {
                LDS64(bh[jj], b_base + (uint32_t)((((ks * 16 + wn * 4 + jj) * 2 + 0) * 32 + lane) * 8));
                LDS64(bl[jj], b_base + (uint32_t)((((ks * 16 + wn * 4 + jj) * 2 + 1) * 32 + lane) * 8));
            }
            #pragma unroll
            for (int ii = 0; ii < 4; ii++)
                #pragma unroll
                for (int jj = 0; jj < 4; jj++) {
                    mma_bf16(acc[ii][jj], ah[ii], bh[jj]);
                    mma_bf16(acc[ii][jj], ah[ii], bl[jj]);
                    mma_bf16(acc[ii][jj], al[ii], bh[jj]);
                }
        }
        __syncthreads();
        if (tid == 0) {
            int jn = i + GSTAGES;
            if (jn < kTiles) {
                fence_async();
                MBAR_EXPECT_TX(FULLB(s), STAGE_BYTES);
                bulk_g2s(a_base, At + (size_t)jn * 16384, 16384, FULLB(s));
                bulk_g2s(b_base, Bt + (size_t)jn * 16384, 16384, FULLB(s));
            }
        }
    }

    const int r = lane >> 2, cc = lane & 3;
    #pragma unroll
    for (int ii = 0; ii < 4; ii++) {
        int m0 = mt * 128 + wm * 64 + ii * 16 + r;
        float* row0 = C + (size_t)m0 * Ndim + nt * 128 + wn * 32 + 2 * cc;
        float* row1 = row0 + 8 * (size_t)Ndim;
        #pragma unroll
        for (int jj = 0; jj < 4; jj++) {
            *(float2*)(row0 + jj * 8) = make_float2(acc[ii][jj][0], acc[ii][jj][1]);
            *(float2*)(row1 + jj * 8) = make_float2(acc[ii][jj][2], acc[ii][jj][3]);
        }
    }
}

// ---------------- rope helper ------------------------------------------------
__device__ __forceinline__ float rope_elem(const float* __restrict__ base, int hd,
                                           const float* __restrict__ cosp,
                                           const float* __restrict__ sinp, int srow)
{
    int j = (hd & 127) >> 1;
    float c = cosp[srow * 64 + j];
    float s = sinp[srow * 64 + j];
    float2 v = *(const float2*)(base + (hd & ~1));
    return (hd & 1) ? (v.x * s + v.y * c) : (v.x * c - v.y * s);
}

// ---------------- repack Q/K/V into fragment-major tiles (rope fused) --------
// Q tile (b,h,qt64): [mtg(4)][ks(16)][lane] float4, tf32, scale folded.
__global__ __launch_bounds__(256) void qrep(const float* __restrict__ Q, float* __restrict__ dst,
                                            const float* __restrict__ cosp,
                                            const float* __restrict__ sinp)
{
    const int qt = blockIdx.x, bh = blockIdx.y;
    const int b = bh >> 4, h = bh & 15;
    const int tid = threadIdx.x;
    const float scale = 0.08838834764831845f;
    float4* out = (float4*)(dst + ((size_t)bh * 32 + qt) * 8192);
    #pragma unroll
    for (int t = 0; t < 8; t++) {
        int u = tid + 256 * t;
        int mtg = u >> 9, ks = (u >> 5) & 15, lane = u & 31;
        int row = b * SS + qt * 64 + mtg * 16 + (lane >> 2);
        int hd = ks * 8 + (lane & 3);
        const float* base0 = Q + (size_t)row * DIM + h * HD;
        const float* base1 = base0 + 8 * (size_t)DIM;
        int s0 = row & (SS - 1), s1 = (row + 8) & (SS - 1);
        out[u] = make_float4(
            tf32r(rope_elem(base0, hd,     cosp, sinp, s0) * scale),
            tf32r(rope_elem(base1, hd,     cosp, sinp, s1) * scale),
            tf32r(rope_elem(base0, hd + 4, cosp, sinp, s0) * scale),
            tf32r(rope_elem(base1, hd + 4, cosp, sinp, s1) * scale));
    }
}
// K tile (b,hk,kvt64): [ds(16)][kvg(8)][lane] float2, tf32, rope fused.
__global__ __launch_bounds__(256) void krep(const float* __restrict__ K, float* __restrict__ dst,
                                            const float* __restrict__ cosp,
                                            const float* __restrict__ sinp)
{
    const int kvt = blockIdx.x, bhk = blockIdx.y;
    const int b = bhk >> 3, hk = bhk & 7;
    const int tid = threadIdx.x;
    float2* out = (float2*)(dst + ((size_t)bhk * 32 + kvt) * 8192);
    #pragma unroll
    for (int t = 0; t < 16; t++) {
        int u = tid + 256 * t;
        int ds = u >> 8, kvg = (u >> 5) & 7, lane = u & 31;
        int kv = kvt * 64 + kvg * 8 + (lane >> 2);
        int d  = ds * 8 + (lane & 3);
        const float* base = K + (size_t)(b * SS + kv) * (NKV * HD) + hk * HD;
        int srow = kv & (SS - 1);
        out[u] = make_float2(tf32r(rope_elem(base, d,     cosp, sinp, srow)),
                             tf32r(rope_elem(base, d + 4, cosp, sinp, srow)));
    }
}
// V tile (b,hk,kvt64): bf16 hi/lo B-frags [t(4)][ng(16)][hl(2)][lane] uint2
__global__ __launch_bounds__(256) void vrep(const float* __restrict__ V, float* __restrict__ dst)
{
    const int kvt = blockIdx.x, bhk = blockIdx.y;
    const int b = bhk >> 3, hk = bhk & 7;
    const int tid = threadIdx.x;
    uint2* out = (uint2*)(dst + ((size_t)bhk * 32 + kvt) * 8192);
    #pragma unroll
    for (int it = 0; it < 8; it++) {
        int u = tid + 256 * it;
        int lane = u & 31, ng = (u >> 5) & 15, t = u >> 9;
        int kv0 = kvt * 64 + t * 16 + (lane & 3) * 2;
        int d   = ng * 8 + (lane >> 2);
        const float* p = V + (size_t)(b * SS + kv0) * (NKV * HD) + hk * HD + d;
        float v00 = p[0];
        float v01 = p[NKV * HD];
        float v10 = p[8 * NKV * HD];
        float v11 = p[9 * NKV * HD];
        uint32_t h0, l0, h1, l1;
        split2(v00, v01, h0, l0);
        split2(v10, v11, h1, l1);
        int bi = ((t * 16 + ng) * 2) * 32 + lane;
        out[bi]      = make_uint2(h0, h1);
        out[bi + 32] = make_uint2(l0, l1);
    }
}

// ---------------- tensor-core flash attention --------------------------------
// BQ=128 (8 warps x 16 rows), BKV=64, 2-stage (K tf32 32KB + V bf16 hi/lo 32KB).
// Q frags in registers, P in registers (bf16 hi/lo), epilogue writes WO A-frags.
#define ATTN_SMEM 131072

__global__ __launch_bounds__(256) void attn_mma(
    const float* __restrict__ Qr, const float* __restrict__ Kr,
    const float* __restrict__ Vr, float* __restrict__ Ap)
{
    extern __shared__ float sm[];
    __shared__ __align__(8) uint64_t bars[2];

    const int tid = threadIdx.x;
    const int lane = tid & 31, wq = tid >> 5;       // 8 warps
    const int qt = 15 - blockIdx.x;                  // heavy CTAs first
    const int bh = blockIdx.y;
    const int b = bh >> 4, h = bh & 15;
    const int bhk = b * 8 + (h >> 1);
    const int niter = 2 * qt + 2;

    uint32_t sbase = smem_u32(sm);
    uint32_t mb = smem_u32(bars);

    // Q fragments -> registers (rows qt*128 + wq*16 .. +15)
    uint32_t qf[16][4];
    {
        const float4* qsrc = (const float4*)(Qr + ((size_t)bh * 32 + qt * 2 + (wq >> 2)) * 8192);
        const int mtg = wq & 3;
        #pragma unroll
        for (int ks = 0; ks < 16; ks++) {
            float4 v = __ldg(&qsrc[(mtg * 16 + ks) * 32 + lane]);
            qf[ks][0] = __float_as_uint(v.x);
            qf[ks][1] = __float_as_uint(v.y);
            qf[ks][2] = __float_as_uint(v.z);
            qf[ks][3] = __float_as_uint(v.w);
        }
    }

    if (tid == 0) { MBAR_INIT(mb, 1); MBAR_INIT(mb + 8, 1); }
    __syncthreads();
    if (tid == 0) {
        fence_async();
        #pragma unroll
        for (int j = 0; j < 2; j++) {
            MBAR_EXPECT_TX(mb + j * 8, 65536);
            bulk_g2s(sbase + j * 65536,         Kr + ((size_t)bhk * 32 + j) * 8192, 32768, mb + j * 8);
            bulk_g2s(sbase + j * 65536 + 32768, Vr + ((size_t)bhk * 32 + j) * 8192, 32768, mb + j * 8);
        }
    }

    float o[16][4];
    #pragma unroll
    for (int i = 0; i < 16; i++)
        #pragma unroll
        for (int q = 0; q < 4; q++) o[i][q] = 0.f;
    float mr0 = -1e30f, mr1 = -1e30f, lr0 = 0.f, lr1 = 0.f;
    const int r0 = lane >> 2;
    const int c0 = (lane & 3) * 2;
    const int qrow = qt * 128 + wq * 16 + r0;

    for (int kb = 0; kb < niter; kb++) {
        const int s = kb & 1;
        mbar_wait(mb + s * 8, (kb >> 1) & 1);
        const uint32_t kbase = sbase + s * 65536;
        const uint32_t vbase = kbase + 32768;

        // QK^T: S[16][64] per warp (Q from registers)
        float sc[8][4];
        #pragma unroll
        for (int ng = 0; ng < 8; ng++)
            #pragma unroll
            for (int q = 0; q < 4; q++) sc[ng][q] = 0.f;
        #pragma unroll
        for (int ks = 0; ks < 16; ks++) {
            #pragma unroll
            for (int ng = 0; ng < 8; ng++) {
                uint32_t kf[2];
                LDS64(kf, kbase + (uint32_t)(((ks * 8 + ng) * 32 + lane) * 8));
                mma_tf32(sc[ng], qf[ks], kf);
            }
        }
        // causal mask (only diagonal-band tiles)
        if (kb >= 2 * qt) {
            #pragma unroll
            for (int ng = 0; ng < 8; ng++) {
                int col = kb * 64 + ng * 8 + c0;
                if (col     > qrow)     sc[ng][0] = -1e30f;
                if (col + 1 > qrow)     sc[ng][1] = -1e30f;
                if (col     > qrow + 8) sc[ng][2] = -1e30f;
                if (col + 1 > qrow + 8) sc[ng][3] = -1e30f;
            }
        }
        // online softmax (rows r0 and r0+8)
        float mA = -1e30f, mB = -1e30f;
        #pragma unroll
        for (int ng = 0; ng < 8; ng++) {
            mA = fmaxf(mA, fmaxf(sc[ng][0], sc[ng][1]));
            mB = fmaxf(mB, fmaxf(sc[ng][2], sc[ng][3]));
        }
        mA = fmaxf(mA, __shfl_xor_sync(0xffffffffu, mA, 1));
        mA = fmaxf(mA, __shfl_xor_sync(0xffffffffu, mA, 2));
        mB = fmaxf(mB, __shfl_xor_sync(0xffffffffu, mB, 1));
        mB = fmaxf(mB, __shfl_xor_sync(0xffffffffu, mB, 2));
        float mnA = fmaxf(mr0, mA), mnB = fmaxf(mr1, mB);
        float fA = __expf(mr0 - mnA), fB = __expf(mr1 - mnB);
        mr0 = mnA; mr1 = mnB;
        float sA = 0.f, sB = 0.f;
        #pragma unroll
        for (int ng = 0; ng < 8; ng++) {
            sc[ng][0] = __expf(sc[ng][0] - mnA);
            sc[ng][1] = __expf(sc[ng][1] - mnA);
            sc[ng][2] = __expf(sc[ng][2] - mnB);
            sc[ng][3] = __expf(sc[ng][3] - mnB);
            sA += sc[ng][0] + sc[ng][1];
            sB += sc[ng][2] + sc[ng][3];
        }
        sA += __shfl_xor_sync(0xffffffffu, sA, 1);
        sA += __shfl_xor_sync(0xffffffffu, sA, 2);
        sB += __shfl_xor_sync(0xffffffffu, sB, 1);
        sB += __shfl_xor_sync(0xffffffffu, sB, 2);
        lr0 = lr0 * fA + sA;
        lr1 = lr1 * fB + sB;
        #pragma unroll
        for (int ng = 0; ng < 16; ng++) {
            o[ng][0] *= fA; o[ng][1] *= fA;
            o[ng][2] *= fB; o[ng][3] *= fB;
        }
        // pack P into bf16 hi/lo A-frags (registers only)
        uint32_t aPh[4][4], aPl[4][4];
        #pragma unroll
        for (int t = 0; t < 4; t++) {
            split2(sc[2*t][0],   sc[2*t][1],   aPh[t][0], aPl[t][0]);
            split2(sc[2*t][2],   sc[2*t][3],   aPh[t][1], aPl[t][1]);
            split2(sc[2*t+1][0], sc[2*t+1][1], aPh[t][2], aPl[t][2]);
            split2(sc[2*t+1][2], sc[2*t+1][3], aPh[t][3], aPl[t][3]);
        }
        // PV: O[16][128] += P[16][64] * V[64][128]  (exact-P x3: PhVh + PlVh + PhVl)
        #pragma unroll
        for (int t = 0; t < 4; t++) {
            #pragma unroll
            for (int ng = 0; ng < 16; ng++) {
                uint32_t vh[2], vl[2];
                uint32_t va = vbase + (uint32_t)((((t * 16 + ng) * 2) * 32 + lane) * 8);
                LDS64(vh, va);
                LDS64(vl, va + 256);
                mma_bf16(o[ng], aPh[t], vh);
                mma_bf16(o[ng], aPl[t], vh);
                mma_bf16(o[ng], aPh[t], vl);
            }
        }
        __syncthreads();
        if (tid == 0 && kb + 2 < niter) {
            int j = kb + 2;
            MBAR_EXPECT_TX(mb + s * 8, 65536);
            bulk_g2s(kbase, Kr + ((size_t)bhk * 32 + j) * 8192, 32768, mb + s * 8);
            bulk_g2s(vbase, Vr + ((size_t)bhk * 32 + j) * 8192, 32768, mb + s * 8);
        }
    }

    // epilogue: write WO-gemm A-fragments (bf16 hi/lo) directly
    float iA = 1.0f / lr0, iB = 1.0f / lr1;
    const int mt = b * 16 + qt;
    #pragma unroll
    for (int t = 0; t < 8; t++) {
        float o0 = o[2*t][0] * iA,   o1 = o[2*t][1] * iA;
        float o2 = o[2*t][2] * iB,   o3 = o[2*t][3] * iB;
        float o4 = o[2*t+1][0] * iA, o5 = o[2*t+1][1] * iA;
        float o6 = o[2*t+1][2] * iB, o7 = o[2*t+1][3] * iB;
        uint32_t h0,h1,h2,h3,l0,l1,l2,l3;
        split2(o0, o1, h0, l0);
        split2(o2, o3, h1, l1);
        split2(o4, o5, h2, l2);
        split2(o6, o7, h3, l3);
        int kglob = h * 128 + t * 16;
        int kc = kglob >> 5, ks2 = t & 1;
        uint4* tb = (uint4*)(Ap + ((size_t)mt * 64 + kc) * 4096);
        int bi = ((ks2 * 8 + wq) * 2) * 32 + lane;
        tb[bi]      = make_uint4(h0, h1, h2, h3);
        tb[bi + 32] = make_uint4(l0, l1, l2, l3);
    }
}

// ---------------- launcher ---------------------------------------------------
extern "C" void kernel_launch(void* const* d_in, const int* in_sizes, int n_in,
                              void* d_out, int out_size)
{
    const float* x    = (const float*)d_in[0];
    const float* fcos = (const float*)d_in[1];
    const float* fsin = (const float*)d_in[2];
    const float* wq   = (const float*)d_in[3];
    const float* wk   = (const float*)d_in[4];
    const float* wv   = (const float*)d_in[5];
    const float* wo   = (const float*)d_in[6];
    float* out = (float*)d_out;

    float *pQ, *pK, *pV, *pxp, *pattp, *pwqp, *pwkp, *pwvp, *pwop, *pQr, *pKr, *pVr;
    cudaGetSymbolAddress((void**)&pQ, g_Q);
    cudaGetSymbolAddress((void**)&pK, g_K);
    cudaGetSymbolAddress((void**)&pV, g_V);
    cudaGetSymbolAddress((void**)&pxp, g_xp);
    cudaGetSymbolAddress((void**)&pattp, g_attp);
    cudaGetSymbolAddress((void**)&pwqp, g_wqp);
    cudaGetSymbolAddress((void**)&pwkp, g_wkp);
    cudaGetSymbolAddress((void**)&pwvp, g_wvp);
    cudaGetSymbolAddress((void**)&pwop, g_wop);
    cudaGetSymbolAddress((void**)&pQr, g_Qr);
    cudaGetSymbolAddress((void**)&pKr, g_Kr);
    cudaGetSymbolAddress((void**)&pVr, g_Vr);

    const size_t gsmem = GSTAGES * STAGE_BYTES + 1024;
    cudaFuncSetAttribute(gemm_mma, cudaFuncAttributeMaxDynamicSharedMemorySize, (int)gsmem);
    cudaFuncSetAttribute(attn_mma, cudaFuncAttributeMaxDynamicSharedMemorySize, ATTN_SMEM);

    // pack weights / activations into bf16 hi/lo fragment-major tiles
    pack_B_bf16<<<dim3(KTILES, DIM/128),      256>>>(wq, pwqp, DIM);
    pack_B_bf16<<<dim3(KTILES, (NKV*HD)/128), 256>>>(wk, pwkp, NKV*HD);
    pack_B_bf16<<<dim3(KTILES, (NKV*HD)/128), 256>>>(wv, pwvp, NKV*HD);
    pack_B_bf16<<<dim3(KTILES, DIM/128),      256>>>(wo, pwop, DIM);
    pack_A_bf16<<<dim3(KTILES, M_ROWS/128),   256>>>(x, pxp, DIM);

    // QKV projections (bf16x3 tensor cores)
    gemm_mma<<<dim3(DIM/128,      M_ROWS/128), 256, gsmem>>>(pxp, pwqp, pQ, DIM,    KTILES);
    gemm_mma<<<dim3((NKV*HD)/128, M_ROWS/128), 256, gsmem>>>(pxp, pwkp, pK, NKV*HD, KTILES);
    gemm_mma<<<dim3((NKV*HD)/128, M_ROWS/128), 256, gsmem>>>(pxp, pwvp, pV, NKV*HD, KTILES);

    // repack into fragment-major tiles (rope fused into qrep/krep)
    qrep<<<dim3(32, BB * NH),  256>>>(pQ, pQr, fcos, fsin);
    krep<<<dim3(32, BB * NKV), 256>>>(pK, pKr, fcos, fsin);
    vrep<<<dim3(32, BB * NKV), 256>>>(pV, pVr);

    // tensor-core flash attention (writes WO A-frags directly)
    attn_mma<<<dim3(16, BB * NH), 256, ATTN_SMEM>>>(pQr, pKr, pVr, pattp);

    // output projection (bf16x3)
    gemm_mma<<<dim3(DIM/128, M_ROWS/128), 256, gsmem>>>(pattp, pwop, out, DIM, KTILES);
}

// round 6
// speedup vs baseline: 4.1388x; 1.0560x over previous
#include <cuda_runtime.h>
#include <cuda_bf16.h>
#include <cstdint>

// Problem constants
#define BB 2
#define SS 2048
#define DIM 2048
#define NH 16
#define NKV 8
#define HD 128
#define M_ROWS (BB*SS)          // 4096
#define KTILES 64               // K=2048 / 32
#define CD 4096                 // fused QKV output width

// ---------------- scratch (device globals: allocation-free) ----------------
__device__ float g_QKV[(size_t)M_ROWS * CD];          // fused QKV output (64MB)
// packed bf16 hi/lo fragment-major buffers
__device__ float g_xp   [(size_t)M_ROWS * DIM];
__device__ float g_attp [(size_t)M_ROWS * DIM];
__device__ float g_wqkvp[(size_t)DIM * CD];           // fused wq|wk|wv (32MB)
__device__ float g_wop  [(size_t)DIM * DIM];
// fragment-major tiles for attention
__device__ float g_Qr[(size_t)BB * NH  * 32 * 8192];  // tf32 frags
__device__ float g_Kr[(size_t)BB * NKV * 32 * 8192];  // tf32 frags
__device__ float g_Vr[(size_t)BB * NKV * 32 * 8192];  // bf16 hi/lo frags

// ---------------- PTX helpers (base sm_90 / sm_80 features only!) -----------
__device__ __forceinline__ uint32_t smem_u32(const void* p) {
    uint32_t a;
    asm("{ .reg .u64 t; cvta.to.shared.u64 t, %1; cvt.u32.u64 %0, t; }" : "=r"(a) : "l"(p));
    return a;
}
__device__ __forceinline__ float tf32r(float x) {
    uint32_t u;
    asm("cvt.rna.tf32.f32 %0, %1;" : "=r"(u) : "f"(x));
    return __uint_as_float(u);
}

#define MBAR_INIT(a, cnt) \
    asm volatile("mbarrier.init.shared.b64 [%0], %1;" :: "r"(a), "r"(cnt) : "memory")
#define MBAR_EXPECT_TX(a, b) \
    asm volatile("mbarrier.arrive.expect_tx.shared.b64 _, [%0], %1;" :: "r"(a), "r"(b) : "memory")

__device__ __forceinline__ void mbar_wait(uint32_t addr, uint32_t phase) {
    uint32_t done;
    asm volatile(
        "{\n\t.reg .pred p;\n\t"
        "mbarrier.try_wait.parity.acquire.cta.shared::cta.b64 p, [%1], %2;\n\t"
        "selp.b32 %0, 1, 0, p;\n\t}"
        : "=r"(done) : "r"(addr), "r"(phase) : "memory");
    if (!done) {
        asm volatile(
            "{\n\t.reg .pred P1;\n\t"
            "W_%=:\n\t"
            "mbarrier.try_wait.parity.acquire.cta.shared::cta.b64 P1, [%0], %1, 0x989680;\n\t"
            "@P1 bra.uni D_%=;\n\t"
            "bra.uni W_%=;\n\t"
            "D_%=:\n\t}"
            :: "r"(addr), "r"(phase) : "memory");
    }
}
__device__ __forceinline__ void bulk_g2s(uint32_t dst, const void* src, uint32_t bytes, uint32_t mbar) {
    asm volatile(
        "cp.async.bulk.shared::cluster.global.mbarrier::complete_tx::bytes [%0], [%1], %2, [%3];"
        :: "r"(dst), "l"(src), "r"(bytes), "r"(mbar) : "memory");
}
__device__ __forceinline__ void fence_async() {
    asm volatile("fence.proxy.async;" ::: "memory");
}

__device__ __forceinline__ void mma_tf32(float* c, const uint32_t* a, const uint32_t* b) {
    asm volatile(
        "mma.sync.aligned.m16n8k8.row.col.f32.tf32.tf32.f32 "
        "{%0,%1,%2,%3}, {%4,%5,%6,%7}, {%8,%9}, {%0,%1,%2,%3};"
        : "+f"(c[0]), "+f"(c[1]), "+f"(c[2]), "+f"(c[3])
        : "r"(a[0]), "r"(a[1]), "r"(a[2]), "r"(a[3]), "r"(b[0]), "r"(b[1]));
}
__device__ __forceinline__ void mma_bf16(float* c, const uint32_t* a, const uint32_t* b) {
    asm volatile(
        "mma.sync.aligned.m16n8k16.row.col.f32.bf16.bf16.f32 "
        "{%0,%1,%2,%3}, {%4,%5,%6,%7}, {%8,%9}, {%0,%1,%2,%3};"
        : "+f"(c[0]), "+f"(c[1]), "+f"(c[2]), "+f"(c[3])
        : "r"(a[0]), "r"(a[1]), "r"(a[2]), "r"(a[3]), "r"(b[0]), "r"(b[1]));
}
#define LDS128(r, addr) \
    asm volatile("ld.shared.v4.b32 {%0,%1,%2,%3}, [%4];" \
        : "=r"((r)[0]), "=r"((r)[1]), "=r"((r)[2]), "=r"((r)[3]) : "r"(addr))
#define LDS64(r, addr) \
    asm volatile("ld.shared.v2.b32 {%0,%1}, [%2];" \
        : "=r"((r)[0]), "=r"((r)[1]) : "r"(addr))

// split fp32 pair into bf16-hi pair and bf16-lo (residual) pair, packed
__device__ __forceinline__ void split2(float x, float y, uint32_t& h, uint32_t& l) {
    __nv_bfloat16 hx = __float2bfloat16_rn(x);
    __nv_bfloat16 hy = __float2bfloat16_rn(y);
    float lx = x - __bfloat162float(hx);
    float ly = y - __bfloat162float(hy);
    __nv_bfloat162 hp = __halves2bfloat162(hx, hy);
    __nv_bfloat162 lp = __floats2bfloat162_rn(lx, ly);
    h = *reinterpret_cast<uint32_t*>(&hp);
    l = *reinterpret_cast<uint32_t*>(&lp);
}

// ---------------- pack A (smem-staged): [M,K] -> bf16 hi/lo A-frag tiles -----
__global__ __launch_bounds__(256) void pack_A_bf16(const float* __restrict__ src,
                                                   float* __restrict__ dst, int K)
{
    __shared__ float sa[128][33];
    const int kc = blockIdx.x, mt = blockIdx.y;
    const int tid = threadIdx.x;
    // coalesced load: 128 rows x 32 cols
    #pragma unroll
    for (int t = 0; t < 4; t++) {
        int u = tid + 256 * t;          // 0..1023 float4s
        int r = u >> 3, c4 = u & 7;
        float4 v = *(const float4*)(src + (size_t)(mt * 128 + r) * K + kc * 32 + c4 * 4);
        sa[r][c4 * 4 + 0] = v.x; sa[r][c4 * 4 + 1] = v.y;
        sa[r][c4 * 4 + 2] = v.z; sa[r][c4 * 4 + 3] = v.w;
    }
    __syncthreads();
    uint4* tb = (uint4*)(dst + (size_t)(mt * (K / 32) + kc) * 4096);
    #pragma unroll
    for (int t = 0; t < 2; t++) {
        int u = tid + 256 * t;
        int ks2 = u >> 8, mtg = (u >> 5) & 7, lane = u & 31;
        int ml = mtg * 16 + (lane >> 2);
        int kl = ks2 * 16 + (lane & 3) * 2;
        uint32_t h0,h1,h2,h3,l0,l1,l2,l3;
        split2(sa[ml][kl],       sa[ml][kl + 1],     h0, l0);
        split2(sa[ml + 8][kl],   sa[ml + 8][kl + 1], h1, l1);
        split2(sa[ml][kl + 8],   sa[ml][kl + 9],     h2, l2);
        split2(sa[ml + 8][kl + 8], sa[ml + 8][kl + 9], h3, l3);
        int bi = ((ks2 * 8 + mtg) * 2) * 32 + lane;
        tb[bi]      = make_uint4(h0, h1, h2, h3);
        tb[bi + 32] = make_uint4(l0, l1, l2, l3);
    }
}

// ---------------- pack B (smem-staged): w[K,N] -> interleaved hi/lo B-frags --
// Tile (nt128, kc32): uint4 slots [ks2(2)][ntg(16)][lane(32)] = (bh0,bh1,bl0,bl1)
__global__ __launch_bounds__(256) void pack_B_bf16(const float* __restrict__ w,
                                                   float* __restrict__ dst, int N)
{
    __shared__ float sb[32][129];
    const int kc = blockIdx.x, nt = blockIdx.y;
    const int tid = threadIdx.x;
    // coalesced load: 32 rows x 128 cols
    #pragma unroll
    for (int t = 0; t < 4; t++) {
        int u = tid + 256 * t;          // 0..1023 float4s
        int r = u >> 5, c4 = u & 31;
        float4 v = *(const float4*)(w + (size_t)(kc * 32 + r) * N + nt * 128 + c4 * 4);
        sb[r][c4 * 4 + 0] = v.x; sb[r][c4 * 4 + 1] = v.y;
        sb[r][c4 * 4 + 2] = v.z; sb[r][c4 * 4 + 3] = v.w;
    }
    __syncthreads();
    uint4* tb = (uint4*)(dst + (size_t)(nt * KTILES + kc) * 4096);
    #pragma unroll
    for (int t = 0; t < 4; t++) {
        int u = tid + 256 * t;          // 0..1023 slots
        int ks2 = u >> 9, ntg = (u >> 5) & 15, lane = u & 31;
        int kl = ks2 * 16 + (lane & 3) * 2;
        int nl = ntg * 8 + (lane >> 2);
        uint32_t bh0, bl0, bh1, bl1;
        split2(sb[kl][nl],     sb[kl + 1][nl], bh0, bl0);
        split2(sb[kl + 8][nl], sb[kl + 9][nl], bh1, bl1);
        tb[(ks2 * 16 + ntg) * 32 + lane] = make_uint4(bh0, bh1, bl0, bl1);
    }
}

// ---------------- bf16x3 GEMM: C[M,N] = A*B (fp32-accurate) ------------------
#define GSTAGES 3
#define STAGE_BYTES 32768

__global__ __launch_bounds__(256, 2) void gemm_mma(
    const float* __restrict__ Ap, const float* __restrict__ Bp,
    float* __restrict__ C, int Ndim, int kTiles)
{
    extern __shared__ float dyn[];
    __shared__ __align__(8) uint64_t mbar[GSTAGES];

    const int tid  = threadIdx.x;
    const int lane = tid & 31;
    const int warp = tid >> 5;
    const int wm = warp >> 2;
    const int wn = warp & 3;
    const int nt = blockIdx.x, mt = blockIdx.y;

    uint32_t sbase = (smem_u32(dyn) + 1023) & ~1023u;
    uint32_t mb = smem_u32(mbar);
    #define FULLB(s) (mb + (s) * 8)

    if (tid == 0) {
        #pragma unroll
        for (int s = 0; s < GSTAGES; s++) MBAR_INIT(FULLB(s), 1);
    }
    __syncthreads();

    const char* At = (const char*)(Ap + (size_t)mt * kTiles * 4096);
    const char* Bt = (const char*)(Bp + (size_t)nt * kTiles * 4096);

    if (tid == 0) {
        fence_async();
        #pragma unroll
        for (int j = 0; j < GSTAGES; j++) {
            MBAR_EXPECT_TX(FULLB(j), STAGE_BYTES);
            bulk_g2s(sbase + j * STAGE_BYTES,         At + (size_t)j * 16384, 16384, FULLB(j));
            bulk_g2s(sbase + j * STAGE_BYTES + 16384, Bt + (size_t)j * 16384, 16384, FULLB(j));
        }
    }

    float acc[4][4][4];
    #pragma unroll
    for (int i = 0; i < 4; i++)
        #pragma unroll
        for (int j = 0; j < 4; j++)
            #pragma unroll
            for (int q = 0; q < 4; q++) acc[i][j][q] = 0.f;

    for (int i = 0; i < kTiles; i++) {
        const int s = i % GSTAGES;
        const uint32_t ph = (i / GSTAGES) & 1;
        mbar_wait(FULLB(s), ph);
        const uint32_t a_base = sbase + s * STAGE_BYTES;
        const uint32_t b_base = a_base + 16384;

        #pragma unroll
        for (int ks = 0; ks < 2; ks++) {
            uint32_t ah[4][4], al[4][4], bf[4][4];
            #pragma unroll
            for (int ii = 0; ii < 4; ii++) {
                LDS128(ah[ii], a_base + (uint32_t)((((ks * 8 + wm * 4 + ii) * 2 + 0) * 32 + lane) * 16));
                LDS128(al[ii], a_base + (uint32_t)((((ks * 8 + wm * 4 + ii) * 2 + 1) * 32 + lane) * 16));
            }
            #pragma unroll
            for (int jj = 0; jj < 4; jj++)
                LDS128(bf[jj], b_base + (uint32_t)(((ks * 16 + wn * 4 + jj) * 32 + lane) * 16));
            #pragma unroll
            for (int ii = 0; ii < 4; ii++)
                #pragma unroll
                for (int jj = 0; jj < 4; jj++) {
                    mma_bf16(acc[ii][jj], ah[ii], &bf[jj][0]);   // hi*hi
                    mma_bf16(acc[ii][jj], ah[ii], &bf[jj][2]);   // hi*lo
                    mma_bf16(acc[ii][jj], al[ii], &bf[jj][0]);   // lo*hi
                }
        }
        __syncthreads();
        if (tid == 0) {
            int jn = i + GSTAGES;
            if (jn < kTiles) {
                fence_async();
                MBAR_EXPECT_TX(FULLB(s), STAGE_BYTES);
                bulk_g2s(a_base, At + (size_t)jn * 16384, 16384, FULLB(s));
                bulk_g2s(b_base, Bt + (size_t)jn * 16384, 16384, FULLB(s));
            }
        }
    }

    const int r = lane >> 2, cc = lane & 3;
    #pragma unroll
    for (int ii = 0; ii < 4; ii++) {
        int m0 = mt * 128 + wm * 64 + ii * 16 + r;
        float* row0 = C + (size_t)m0 * Ndim + nt * 128 + wn * 32 + 2 * cc;
        float* row1 = row0 + 8 * (size_t)Ndim;
        #pragma unroll
        for (int jj = 0; jj < 4; jj++) {
            *(float2*)(row0 + jj * 8) = make_float2(acc[ii][jj][0], acc[ii][jj][1]);
            *(float2*)(row1 + jj * 8) = make_float2(acc[ii][jj][2], acc[ii][jj][3]);
        }
    }
}

// ---------------- rope helper ------------------------------------------------
__device__ __forceinline__ float rope_elem(const float* __restrict__ base, int hd,
                                           const float* __restrict__ cosp,
                                           const float* __restrict__ sinp, int srow)
{
    int j = (hd & 127) >> 1;
    float c = cosp[srow * 64 + j];
    float s = sinp[srow * 64 + j];
    float2 v = *(const float2*)(base + (hd & ~1));
    return (hd & 1) ? (v.x * s + v.y * c) : (v.x * c - v.y * s);
}

// ---------------- repack Q/K/V from fused QKV into frag tiles (rope fused) ---
__global__ __launch_bounds__(256) void qrep(const float* __restrict__ QKV, float* __restrict__ dst,
                                            const float* __restrict__ cosp,
                                            const float* __restrict__ sinp)
{
    const int qt = blockIdx.x, bh = blockIdx.y;
    const int b = bh >> 4, h = bh & 15;
    const int tid = threadIdx.x;
    const float scale = 0.08838834764831845f;
    float4* out = (float4*)(dst + ((size_t)bh * 32 + qt) * 8192);
    #pragma unroll
    for (int t = 0; t < 8; t++) {
        int u = tid + 256 * t;
        int mtg = u >> 9, ks = (u >> 5) & 15, lane = u & 31;
        int row = b * SS + qt * 64 + mtg * 16 + (lane >> 2);
        int hd = ks * 8 + (lane & 3);
        const float* base0 = QKV + (size_t)row * CD + h * HD;
        const float* base1 = base0 + 8 * (size_t)CD;
        int s0 = row & (SS - 1), s1 = (row + 8) & (SS - 1);
        out[u] = make_float4(
            tf32r(rope_elem(base0, hd,     cosp, sinp, s0) * scale),
            tf32r(rope_elem(base1, hd,     cosp, sinp, s1) * scale),
            tf32r(rope_elem(base0, hd + 4, cosp, sinp, s0) * scale),
            tf32r(rope_elem(base1, hd + 4, cosp, sinp, s1) * scale));
    }
}
__global__ __launch_bounds__(256) void krep(const float* __restrict__ QKV, float* __restrict__ dst,
                                            const float* __restrict__ cosp,
                                            const float* __restrict__ sinp)
{
    const int kvt = blockIdx.x, bhk = blockIdx.y;
    const int b = bhk >> 3, hk = bhk & 7;
    const int tid = threadIdx.x;
    float2* out = (float2*)(dst + ((size_t)bhk * 32 + kvt) * 8192);
    #pragma unroll
    for (int t = 0; t < 16; t++) {
        int u = tid + 256 * t;
        int ds = u >> 8, kvg = (u >> 5) & 7, lane = u & 31;
        int kv = kvt * 64 + kvg * 8 + (lane >> 2);
        int d  = ds * 8 + (lane & 3);
        const float* base = QKV + (size_t)(b * SS + kv) * CD + 2048 + hk * HD;
        int srow = kv & (SS - 1);
        out[u] = make_float2(tf32r(rope_elem(base, d,     cosp, sinp, srow)),
                             tf32r(rope_elem(base, d + 4, cosp, sinp, srow)));
    }
}
__global__ __launch_bounds__(256) void vrep(const float* __restrict__ QKV, float* __restrict__ dst)
{
    const int kvt = blockIdx.x, bhk = blockIdx.y;
    const int b = bhk >> 3, hk = bhk & 7;
    const int tid = threadIdx.x;
    uint2* out = (uint2*)(dst + ((size_t)bhk * 32 + kvt) * 8192);
    #pragma unroll
    for (int it = 0; it < 8; it++) {
        int u = tid + 256 * it;
        int lane = u & 31, ng = (u >> 5) & 15, t = u >> 9;
        int kv0 = kvt * 64 + t * 16 + (lane & 3) * 2;
        int d   = ng * 8 + (lane >> 2);
        const float* p = QKV + (size_t)(b * SS + kv0) * CD + 3072 + hk * HD + d;
        float v00 = p[0];
        float v01 = p[CD];
        float v10 = p[8 * CD];
        float v11 = p[9 * CD];
        uint32_t h0, l0, h1, l1;
        split2(v00, v01, h0, l0);
        split2(v10, v11, h1, l1);
        int bi = ((t * 16 + ng) * 2) * 32 + lane;
        out[bi]      = make_uint2(h0, h1);
        out[bi + 32] = make_uint2(l0, l1);
    }
}

// ---------------- tensor-core flash attention --------------------------------
#define ATTN_SMEM 131072

__global__ __launch_bounds__(256) void attn_mma(
    const float* __restrict__ Qr, const float* __restrict__ Kr,
    const float* __restrict__ Vr, float* __restrict__ Ap)
{
    extern __shared__ float sm[];
    __shared__ __align__(8) uint64_t bars[2];

    const int tid = threadIdx.x;
    const int lane = tid & 31, wq = tid >> 5;
    const int qt = 15 - blockIdx.x;                  // heavy CTAs first
    const int bh = blockIdx.y;
    const int b = bh >> 4, h = bh & 15;
    const int bhk = b * 8 + (h >> 1);
    const int niter = 2 * qt + 2;

    uint32_t sbase = smem_u32(sm);
    uint32_t mb = smem_u32(bars);

    uint32_t qf[16][4];
    {
        const float4* qsrc = (const float4*)(Qr + ((size_t)bh * 32 + qt * 2 + (wq >> 2)) * 8192);
        const int mtg = wq & 3;
        #pragma unroll
        for (int ks = 0; ks < 16; ks++) {
            float4 v = __ldg(&qsrc[(mtg * 16 + ks) * 32 + lane]);
            qf[ks][0] = __float_as_uint(v.x);
            qf[ks][1] = __float_as_uint(v.y);
            qf[ks][2] = __float_as_uint(v.z);
            qf[ks][3] = __float_as_uint(v.w);
        }
    }

    if (tid == 0) { MBAR_INIT(mb, 1); MBAR_INIT(mb + 8, 1); }
    __syncthreads();
    if (tid == 0) {
        fence_async();
        #pragma unroll
        for (int j = 0; j < 2; j++) {
            MBAR_EXPECT_TX(mb + j * 8, 65536);
            bulk_g2s(sbase + j * 65536,         Kr + ((size_t)bhk * 32 + j) * 8192, 32768, mb + j * 8);
            bulk_g2s(sbase + j * 65536 + 32768, Vr + ((size_t)bhk * 32 + j) * 8192, 32768, mb + j * 8);
        }
    }

    float o[16][4];
    #pragma unroll
    for (int i = 0; i < 16; i++)
        #pragma unroll
        for (int q = 0; q < 4; q++) o[i][q] = 0.f;
    float mr0 = -1e30f, mr1 = -1e30f, lr0 = 0.f, lr1 = 0.f;
    const int r0 = lane >> 2;
    const int c0 = (lane & 3) * 2;
    const int qrow = qt * 128 + wq * 16 + r0;

    for (int kb = 0; kb < niter; kb++) {
        const int s = kb & 1;
        mbar_wait(mb + s * 8, (kb >> 1) & 1);
        const uint32_t kbase = sbase + s * 65536;
        const uint32_t vbase = kbase + 32768;

        float sc[8][4];
        #pragma unroll
        for (int ng = 0; ng < 8; ng++)
            #pragma unroll
            for (int q = 0; q < 4; q++) sc[ng][q] = 0.f;
        #pragma unroll
        for (int ks = 0; ks < 16; ks++) {
            #pragma unroll
            for (int ng = 0; ng < 8; ng++) {
                uint32_t kf[2];
                LDS64(kf, kbase + (uint32_t)(((ks * 8 + ng) * 32 + lane) * 8));
                mma_tf32(sc[ng], qf[ks], kf);
            }
        }
        if (kb >= 2 * qt) {
            #pragma unroll
            for (int ng = 0; ng < 8; ng++) {
                int col = kb * 64 + ng * 8 + c0;
                if (col     > qrow)     sc[ng][0] = -1e30f;
                if (col + 1 > qrow)     sc[ng][1] = -1e30f;
                if (col     > qrow + 8) sc[ng][2] = -1e30f;
                if (col + 1 > qrow + 8) sc[ng][3] = -1e30f;
            }
        }
        float mA = -1e30f, mB = -1e30f;
        #pragma unroll
        for (int ng = 0; ng < 8; ng++) {
            mA = fmaxf(mA, fmaxf(sc[ng][0], sc[ng][1]));
            mB = fmaxf(mB, fmaxf(sc[ng][2], sc[ng][3]));
        }
        mA = fmaxf(mA, __shfl_xor_sync(0xffffffffu, mA, 1));
        mA = fmaxf(mA, __shfl_xor_sync(0xffffffffu, mA, 2));
        mB = fmaxf(mB, __shfl_xor_sync(0xffffffffu, mB, 1));
        mB = fmaxf(mB, __shfl_xor_sync(0xffffffffu, mB, 2));
        float mnA = fmaxf(mr0, mA), mnB = fmaxf(mr1, mB);
        float fA = __expf(mr0 - mnA), fB = __expf(mr1 - mnB);
        mr0 = mnA; mr1 = mnB;
        float sA = 0.f, sB = 0.f;
        #pragma unroll
        for (int ng = 0; ng < 8; ng++) {
            sc[ng][0] = __expf(sc[ng][0] - mnA);
            sc[ng][1] = __expf(sc[ng][1] - mnA);
            sc[ng][2] = __expf(sc[ng][2] - mnB);
            sc[ng][3] = __expf(sc[ng][3] - mnB);
            sA += sc[ng][0] + sc[ng][1];
            sB += sc[ng][2] + sc[ng][3];
        }
        sA += __shfl_xor_sync(0xffffffffu, sA, 1);
        sA += __shfl_xor_sync(0xffffffffu, sA, 2);
        sB += __shfl_xor_sync(0xffffffffu, sB, 1);
        sB += __shfl_xor_sync(0xffffffffu, sB, 2);
        lr0 = lr0 * fA + sA;
        lr1 = lr1 * fB + sB;
        #pragma unroll
        for (int ng = 0; ng < 16; ng++) {
            o[ng][0] *= fA; o[ng][1] *= fA;
            o[ng][2] *= fB; o[ng][3] *= fB;
        }
        uint32_t aPh[4][4], aPl[4][4];
        #pragma unroll
        for (int t = 0; t < 4; t++) {
            split2(sc[2*t][0],   sc[2*t][1],   aPh[t][0], aPl[t][0]);
            split2(sc[2*t][2],   sc[2*t][3],   aPh[t][1], aPl[t][1]);
            split2(sc[2*t+1][0], sc[2*t+1][1], aPh[t][2], aPl[t][2]);
            split2(sc[2*t+1][2], sc[2*t+1][3], aPh[t][3], aPl[t][3]);
        }
        #pragma unroll
        for (int t = 0; t < 4; t++) {
            #pragma unroll
            for (int ng = 0; ng < 16; ng++) {
                uint32_t vh[2], vl[2];
                uint32_t va = vbase + (uint32_t)((((t * 16 + ng) * 2) * 32 + lane) * 8);
                LDS64(vh, va);
                LDS64(vl, va + 256);
                mma_bf16(o[ng], aPh[t], vh);
                mma_bf16(o[ng], aPl[t], vh);
                mma_bf16(o[ng], aPh[t], vl);
            }
        }
        __syncthreads();
        if (tid == 0 && kb + 2 < niter) {
            int j = kb + 2;
            MBAR_EXPECT_TX(mb + s * 8, 65536);
            bulk_g2s(kbase, Kr + ((size_t)bhk * 32 + j) * 8192, 32768, mb + s * 8);
            bulk_g2s(vbase, Vr + ((size_t)bhk * 32 + j) * 8192, 32768, mb + s * 8);
        }
    }

    float iA = 1.0f / lr0, iB = 1.0f / lr1;
    const int mt = b * 16 + qt;
    #pragma unroll
    for (int t = 0; t < 8; t++) {
        float o0 = o[2*t][0] * iA,   o1 = o[2*t][1] * iA;
        float o2 = o[2*t][2] * iB,   o3 = o[2*t][3] * iB;
        float o4 = o[2*t+1][0] * iA, o5 = o[2*t+1][1] * iA;
        float o6 = o[2*t+1][2] * iB, o7 = o[2*t+1][3] * iB;
        uint32_t h0,h1,h2,h3,l0,l1,l2,l3;
        split2(o0, o1, h0, l0);
        split2(o2, o3, h1, l1);
        split2(o4, o5, h2, l2);
        split2(o6, o7, h3, l3);
        int kglob = h * 128 + t * 16;
        int kc = kglob >> 5, ks2 = t & 1;
        uint4* tb = (uint4*)(Ap + ((size_t)mt * 64 + kc) * 4096);
        int bi = ((ks2 * 8 + wq) * 2) * 32 + lane;
        tb[bi]      = make_uint4(h0, h1, h2, h3);
        tb[bi + 32] = make_uint4(l0, l1, l2, l3);
    }
}

// ---------------- launcher ---------------------------------------------------
extern "C" void kernel_launch(void* const* d_in, const int* in_sizes, int n_in,
                              void* d_out, int out_size)
{
    const float* x    = (const float*)d_in[0];
    const float* fcos = (const float*)d_in[1];
    const float* fsin = (const float*)d_in[2];
    const float* wq   = (const float*)d_in[3];
    const float* wk   = (const float*)d_in[4];
    const float* wv   = (const float*)d_in[5];
    const float* wo   = (const float*)d_in[6];
    float* out = (float*)d_out;

    float *pQKV, *pxp, *pattp, *pwqkvp, *pwop, *pQr, *pKr, *pVr;
    cudaGetSymbolAddress((void**)&pQKV, g_QKV);
    cudaGetSymbolAddress((void**)&pxp, g_xp);
    cudaGetSymbolAddress((void**)&pattp, g_attp);
    cudaGetSymbolAddress((void**)&pwqkvp, g_wqkvp);
    cudaGetSymbolAddress((void**)&pwop, g_wop);
    cudaGetSymbolAddress((void**)&pQr, g_Qr);
    cudaGetSymbolAddress((void**)&pKr, g_Kr);
    cudaGetSymbolAddress((void**)&pVr, g_Vr);

    const size_t gsmem = GSTAGES * STAGE_BYTES + 1024;
    cudaFuncSetAttribute(gemm_mma, cudaFuncAttributeMaxDynamicSharedMemorySize, (int)gsmem);
    cudaFuncSetAttribute(attn_mma, cudaFuncAttributeMaxDynamicSharedMemorySize, ATTN_SMEM);

    const size_t NT_STRIDE = (size_t)KTILES * 4096;   // floats per nt row of tiles

    // fused B pack: wq -> nt 0..15, wk -> nt 16..23, wv -> nt 24..31
    pack_B_bf16<<<dim3(KTILES, DIM/128),      256>>>(wq, pwqkvp,                  DIM);
    pack_B_bf16<<<dim3(KTILES, (NKV*HD)/128), 256>>>(wk, pwqkvp + 16 * NT_STRIDE, NKV*HD);
    pack_B_bf16<<<dim3(KTILES, (NKV*HD)/128), 256>>>(wv, pwqkvp + 24 * NT_STRIDE, NKV*HD);
    pack_B_bf16<<<dim3(KTILES, DIM/128),      256>>>(wo, pwop, DIM);
    pack_A_bf16<<<dim3(KTILES, M_ROWS/128),   256>>>(x, pxp, DIM);

    // fused QKV projection (single GEMM, N=4096)
    gemm_mma<<<dim3(CD/128, M_ROWS/128), 256, gsmem>>>(pxp, pwqkvp, pQKV, CD, KTILES);

    // repack into fragment-major tiles (rope fused into qrep/krep)
    qrep<<<dim3(32, BB * NH),  256>>>(pQKV, pQr, fcos, fsin);
    krep<<<dim3(32, BB * NKV), 256>>>(pQKV, pKr, fcos, fsin);
    vrep<<<dim3(32, BB * NKV), 256>>>(pQKV, pVr);

    // tensor-core flash attention (writes WO A-frags directly)
    attn_mma<<<dim3(16, BB * NH), 256, ATTN_SMEM>>>(pQr, pKr, pVr, pattp);

    // output projection (bf16x3)
    gemm_mma<<<dim3(DIM/128, M_ROWS/128), 256, gsmem>>>(pattp, pwop, out, DIM, KTILES);
}